// round 1
// baseline (speedup 1.0000x reference)
#include <cuda_runtime.h>
#include <math.h>

// Problem constants
#define EMB    2048
#define HEADS  16
#define HEADD  128
#define BATCH  4
#define SEQ    2048
#define MROWS  (BATCH * SEQ)        // 8192
#define BHSD_ELEMS (BATCH * HEADS * SEQ * HEADD)  // 16777216

// Scratch (device globals: allocation-free)
__device__ float g_q[BHSD_ELEMS];
__device__ float g_k[BHSD_ELEMS];
__device__ float g_v[BHSD_ELEMS];
__device__ float g_ctx[(size_t)MROWS * EMB];

// ---------------------------------------------------------------------------
// SGEMM (NT): C[m,n] = sum_k A[m,k] * W[n,k] + bias[n]
// A: [M x K] row-major, W: [N x K] row-major. Tile 128x128x16, 8x8/thread.
// out_mode 0: scatter to [B,H,S,D] (n = h*128+d, m = b*2048+s)
// out_mode 1: row-major [M x EMB]
// ---------------------------------------------------------------------------
__global__ __launch_bounds__(256, 2)
void sgemm_nt(const float* __restrict__ A, const float* __restrict__ W,
              const float* __restrict__ bias, float* __restrict__ C,
              int out_mode)
{
    const int K = EMB;
    __shared__ float As[16][132];
    __shared__ float Bs[16][132];

    int tid = threadIdx.x;
    int m0 = blockIdx.y * 128;
    int n0 = blockIdx.x * 128;
    int tx = tid & 15;
    int ty = tid >> 4;
    int lr = tid >> 2;          // 0..63
    int lc = (tid & 3) << 2;    // 0,4,8,12

    float acc[8][8];
#pragma unroll
    for (int i = 0; i < 8; i++)
#pragma unroll
        for (int j = 0; j < 8; j++) acc[i][j] = 0.0f;

    const float* Aptr = A + (size_t)m0 * K;
    const float* Wptr = W + (size_t)n0 * K;

    for (int k0 = 0; k0 < K; k0 += 16) {
#pragma unroll
        for (int h = 0; h < 2; h++) {
            int r = lr + h * 64;
            float4 va = *(const float4*)(Aptr + (size_t)r * K + k0 + lc);
            As[lc + 0][r] = va.x;
            As[lc + 1][r] = va.y;
            As[lc + 2][r] = va.z;
            As[lc + 3][r] = va.w;
            float4 vb = *(const float4*)(Wptr + (size_t)r * K + k0 + lc);
            Bs[lc + 0][r] = vb.x;
            Bs[lc + 1][r] = vb.y;
            Bs[lc + 2][r] = vb.z;
            Bs[lc + 3][r] = vb.w;
        }
        __syncthreads();

#pragma unroll
        for (int kk = 0; kk < 16; kk++) {
            float a[8], b[8];
            *(float4*)&a[0] = *(const float4*)&As[kk][ty * 8];
            *(float4*)&a[4] = *(const float4*)&As[kk][ty * 8 + 4];
            *(float4*)&b[0] = *(const float4*)&Bs[kk][tx * 8];
            *(float4*)&b[4] = *(const float4*)&Bs[kk][tx * 8 + 4];
#pragma unroll
            for (int i = 0; i < 8; i++)
#pragma unroll
                for (int j = 0; j < 8; j++)
                    acc[i][j] += a[i] * b[j];
        }
        __syncthreads();
    }

    int nbase = n0 + tx * 8;
#pragma unroll
    for (int i = 0; i < 8; i++) {
        int m = m0 + ty * 8 + i;
        float o[8];
#pragma unroll
        for (int j = 0; j < 8; j++) o[j] = acc[i][j] + bias[nbase + j];

        if (out_mode == 0) {
            int b  = m >> 11;
            int s  = m & 2047;
            int hh = nbase >> 7;
            int d  = nbase & 127;
            float* dst = C + ((((size_t)b * HEADS + hh) * SEQ + s) * HEADD + d);
            *(float4*)(dst)     = make_float4(o[0], o[1], o[2], o[3]);
            *(float4*)(dst + 4) = make_float4(o[4], o[5], o[6], o[7]);
        } else {
            float* dst = C + (size_t)m * EMB + nbase;
            *(float4*)(dst)     = make_float4(o[0], o[1], o[2], o[3]);
            *(float4*)(dst + 4) = make_float4(o[4], o[5], o[6], o[7]);
        }
    }
}

// ---------------------------------------------------------------------------
// Flash attention, fp32, causal. One block = 64 queries of one (b,h).
// Qt/Kt: d-major transposed tiles [128][68]; Vs: [64][132]; Pt: [64][65].
// Threads 16x16: scores 4x4/thread, O accum 4x8/thread.
// ---------------------------------------------------------------------------
#define QT_STR 68
#define VS_STR 132
#define PT_STR 65
#define FLASH_SMEM_FLOATS (128 * QT_STR * 2 + 64 * VS_STR + 64 * PT_STR)
#define FLASH_SMEM_BYTES  (FLASH_SMEM_FLOATS * 4)

__global__ __launch_bounds__(256, 1)
void flash_attn(const float* __restrict__ q, const float* __restrict__ k,
                const float* __restrict__ v, float* __restrict__ ctx)
{
    extern __shared__ float sm[];
    float* Qt = sm;                       // [128][68]
    float* Kt = Qt + 128 * QT_STR;        // [128][68]
    float* Vs = Kt + 128 * QT_STR;        // [64][132]
    float* Pt = Vs + 64 * VS_STR;         // [64][65]

    int tid = threadIdx.x;
    int w   = tid >> 5;
    int l   = tid & 31;
    int r8  = l >> 2;       // 0..7
    int dc4 = l & 3;        // 0..3
    int tx  = tid & 15;
    int ty  = tid >> 4;

    int q0 = blockIdx.x * 64;
    int bh = blockIdx.y;
    const float* qp = q + (size_t)bh * SEQ * HEADD;
    const float* kp = k + (size_t)bh * SEQ * HEADD;
    const float* vp = v + (size_t)bh * SEQ * HEADD;

    const float scale = 0.08838834764831845f;  // 1/sqrt(128)

    // Load Q transposed (d-major), pre-scaled
#pragma unroll
    for (int it = 0; it < 8; it++) {
        int row = it * 8 + r8;
        int dch = w * 4 + dc4;
        float4 val = *(const float4*)&qp[(size_t)(q0 + row) * HEADD + dch * 4];
        Qt[(dch * 4 + 0) * QT_STR + row] = val.x * scale;
        Qt[(dch * 4 + 1) * QT_STR + row] = val.y * scale;
        Qt[(dch * 4 + 2) * QT_STR + row] = val.z * scale;
        Qt[(dch * 4 + 3) * QT_STR + row] = val.w * scale;
    }

    float acc[4][8];
#pragma unroll
    for (int i = 0; i < 4; i++)
#pragma unroll
        for (int j = 0; j < 8; j++) acc[i][j] = 0.0f;

    float m_run[4], l_run[4];
#pragma unroll
    for (int i = 0; i < 4; i++) { m_run[i] = -1e30f; l_run[i] = 0.0f; }

    int kb_end = blockIdx.x;
    for (int kb = 0; kb <= kb_end; kb++) {
        __syncthreads();  // prior PV done with Vs/Pt; Qt writes visible before 1st use

        // Load K transposed
#pragma unroll
        for (int it = 0; it < 8; it++) {
            int row = it * 8 + r8;
            int dch = w * 4 + dc4;
            float4 val = *(const float4*)&kp[(size_t)(kb * 64 + row) * HEADD + dch * 4];
            Kt[(dch * 4 + 0) * QT_STR + row] = val.x;
            Kt[(dch * 4 + 1) * QT_STR + row] = val.y;
            Kt[(dch * 4 + 2) * QT_STR + row] = val.z;
            Kt[(dch * 4 + 3) * QT_STR + row] = val.w;
        }
        // Load V (row-major, coalesced)
#pragma unroll
        for (int it = 0; it < 8; it++) {
            int idx = tid + it * 256;
            int row = idx >> 5;
            int c   = idx & 31;
            *(float4*)&Vs[row * VS_STR + c * 4] =
                *(const float4*)&vp[(size_t)(kb * 64 + row) * HEADD + c * 4];
        }
        __syncthreads();

        // Scores S = Q K^T (pre-scaled): 4x4 per thread
        float s[4][4];
#pragma unroll
        for (int i = 0; i < 4; i++)
#pragma unroll
            for (int j = 0; j < 4; j++) s[i][j] = 0.0f;

#pragma unroll 4
        for (int dd = 0; dd < 128; dd++) {
            float4 af = *(const float4*)&Qt[dd * QT_STR + ty * 4];
            float4 bf = *(const float4*)&Kt[dd * QT_STR + tx * 4];
            float av[4] = {af.x, af.y, af.z, af.w};
            float bv[4] = {bf.x, bf.y, bf.z, bf.w};
#pragma unroll
            for (int i = 0; i < 4; i++)
#pragma unroll
                for (int j = 0; j < 4; j++)
                    s[i][j] += av[i] * bv[j];
        }

        // Causal mask (diagonal block only; keys/queries share base q0)
        if (kb == kb_end) {
#pragma unroll
            for (int i = 0; i < 4; i++)
#pragma unroll
                for (int j = 0; j < 4; j++)
                    if (tx * 4 + j > ty * 4 + i) s[i][j] = -1e30f;
        }

        // Online softmax (16-lane row groups)
        float alpha[4];
#pragma unroll
        for (int i = 0; i < 4; i++) {
            float mx = fmaxf(fmaxf(s[i][0], s[i][1]), fmaxf(s[i][2], s[i][3]));
#pragma unroll
            for (int o = 8; o > 0; o >>= 1)
                mx = fmaxf(mx, __shfl_xor_sync(0xffffffffu, mx, o));
            float mn = fmaxf(m_run[i], mx);
            alpha[i] = __expf(m_run[i] - mn);
            m_run[i] = mn;
            float rs = 0.0f;
#pragma unroll
            for (int j = 0; j < 4; j++) {
                s[i][j] = __expf(s[i][j] - mn);
                rs += s[i][j];
            }
#pragma unroll
            for (int o = 8; o > 0; o >>= 1)
                rs += __shfl_xor_sync(0xffffffffu, rs, o);
            l_run[i] = l_run[i] * alpha[i] + rs;
        }

        // Rescale accumulators
#pragma unroll
        for (int i = 0; i < 4; i++)
#pragma unroll
            for (int j = 0; j < 8; j++) acc[i][j] *= alpha[i];

        // Stage P transposed: Pt[key][qrow]
#pragma unroll
        for (int i = 0; i < 4; i++)
#pragma unroll
            for (int j = 0; j < 4; j++)
                Pt[(tx * 4 + j) * PT_STR + (ty * 4 + i)] = s[i][j];
        __syncthreads();

        // O += P @ V
#pragma unroll 4
        for (int kk = 0; kk < 64; kk++) {
            float av[4];
#pragma unroll
            for (int i = 0; i < 4; i++) av[i] = Pt[kk * PT_STR + ty * 4 + i];
            float4 b0 = *(const float4*)&Vs[kk * VS_STR + tx * 8];
            float4 b1 = *(const float4*)&Vs[kk * VS_STR + tx * 8 + 4];
            float bv[8] = {b0.x, b0.y, b0.z, b0.w, b1.x, b1.y, b1.z, b1.w};
#pragma unroll
            for (int i = 0; i < 4; i++)
#pragma unroll
                for (int j = 0; j < 8; j++)
                    acc[i][j] += av[i] * bv[j];
        }
    }

    // Epilogue: ctx[b, s, h*128 + d] = O / l
    int b  = bh >> 4;
    int hh = bh & 15;
#pragma unroll
    for (int i = 0; i < 4; i++) {
        float inv = 1.0f / l_run[i];
        int srow = q0 + ty * 4 + i;
        float* op = g_ctx + ((size_t)(b * SEQ + srow)) * EMB + hh * HEADD + tx * 8;
        *(float4*)(op)     = make_float4(acc[i][0] * inv, acc[i][1] * inv,
                                         acc[i][2] * inv, acc[i][3] * inv);
        *(float4*)(op + 4) = make_float4(acc[i][4] * inv, acc[i][5] * inv,
                                         acc[i][6] * inv, acc[i][7] * inv);
    }
    (void)ctx;
}

// ---------------------------------------------------------------------------
extern "C" void kernel_launch(void* const* d_in, const int* in_sizes, int n_in,
                              void* d_out, int out_size)
{
    const float* x  = (const float*)d_in[0];
    // d_in[1] = attn_mask (pure causal; implemented analytically)
    const float* Wq = (const float*)d_in[2];
    const float* bq = (const float*)d_in[3];
    const float* Wk = (const float*)d_in[4];
    const float* bk = (const float*)d_in[5];
    const float* Wv = (const float*)d_in[6];
    const float* bv = (const float*)d_in[7];
    const float* Wo = (const float*)d_in[8];
    const float* bo = (const float*)d_in[9];
    float* out = (float*)d_out;

    float *qb, *kb, *vb, *cb;
    cudaGetSymbolAddress((void**)&qb, g_q);
    cudaGetSymbolAddress((void**)&kb, g_k);
    cudaGetSymbolAddress((void**)&vb, g_v);
    cudaGetSymbolAddress((void**)&cb, g_ctx);

    dim3 gg(EMB / 128, MROWS / 128);  // (16, 64)
    sgemm_nt<<<gg, 256>>>(x, Wq, bq, qb, 0);
    sgemm_nt<<<gg, 256>>>(x, Wk, bk, kb, 0);
    sgemm_nt<<<gg, 256>>>(x, Wv, bv, vb, 0);

    cudaFuncSetAttribute(flash_attn, cudaFuncAttributeMaxDynamicSharedMemorySize,
                         FLASH_SMEM_BYTES);
    flash_attn<<<dim3(SEQ / 64, BATCH * HEADS), 256, FLASH_SMEM_BYTES>>>(qb, kb, vb, cb);

    sgemm_nt<<<gg, 256>>>(cb, Wo, bo, out, 1);
}

// round 3
// speedup vs baseline: 1.6763x; 1.6763x over previous
#include <cuda_runtime.h>
#include <cuda_bf16.h>
#include <math.h>
#include <cstdint>

// Problem constants
#define EMB    2048
#define HEADS  16
#define HEADD  128
#define BATCH  4
#define SEQ    2048
#define MROWS  (BATCH * SEQ)        // 8192
#define KDIM   EMB

// ---------------------------------------------------------------------------
// Scratch (device globals: allocation-free)
// ---------------------------------------------------------------------------
__device__ __nv_bfloat16 g_xh[(size_t)MROWS * EMB];   // X hi (reused for ctx hi)
__device__ __nv_bfloat16 g_xl[(size_t)MROWS * EMB];   // X lo (reused for ctx lo)
__device__ __nv_bfloat16 g_wh[4][(size_t)EMB * EMB];  // Wq,Wk,Wv,Wo hi
__device__ __nv_bfloat16 g_wl[4][(size_t)EMB * EMB];  // lo
__device__ float g_q[(size_t)MROWS * EMB];            // [B,S,H,D] == row-major [M][EMB]
__device__ float g_k[(size_t)MROWS * EMB];
__device__ float g_v[(size_t)MROWS * EMB];
__device__ float g_ctx[(size_t)MROWS * EMB];

// ---------------------------------------------------------------------------
// PTX helpers (compute_103-safe: no 'a' features)
// ---------------------------------------------------------------------------
__device__ __forceinline__ uint32_t smem_u32(const void* p) {
    uint32_t a;
    asm("{ .reg .u64 t; cvta.to.shared.u64 t, %1; cvt.u32.u64 %0, t; }" : "=r"(a) : "l"(p));
    return a;
}

#define CP_ASYNC16(dst, src) \
    asm volatile("cp.async.cg.shared.global [%0], [%1], 16;" :: "r"(dst), "l"(src) : "memory")
#define CP_COMMIT() asm volatile("cp.async.commit_group;" ::: "memory")
#define CP_WAIT1()  asm volatile("cp.async.wait_group 1;" ::: "memory")

#define LDSM4(r, a)                                                              \
    asm volatile("ldmatrix.sync.aligned.m8n8.x4.shared.b16 {%0,%1,%2,%3}, [%4];" \
        : "=r"((r)[0]), "=r"((r)[1]), "=r"((r)[2]), "=r"((r)[3]) : "r"(a))

#define MMA16816(d, a, b0, b1)                                                   \
    asm volatile("mma.sync.aligned.m16n8k16.row.col.f32.bf16.bf16.f32 "          \
        "{%0,%1,%2,%3}, {%4,%5,%6,%7}, {%8,%9}, {%0,%1,%2,%3};"                  \
        : "+f"((d)[0]), "+f"((d)[1]), "+f"((d)[2]), "+f"((d)[3])                  \
        : "r"((a)[0]), "r"((a)[1]), "r"((a)[2]), "r"((a)[3]), "r"(b0), "r"(b1))

// ---------------------------------------------------------------------------
// Split fp32 -> bf16 hi + bf16 lo  (vectorized x4)
// ---------------------------------------------------------------------------
__global__ void split_bf16(const float* __restrict__ in,
                           __nv_bfloat16* __restrict__ hi,
                           __nv_bfloat16* __restrict__ lo, int n4)
{
    int i = blockIdx.x * blockDim.x + threadIdx.x;
    if (i >= n4) return;
    float4 v = ((const float4*)in)[i];
    __nv_bfloat16 h0 = __float2bfloat16(v.x);
    __nv_bfloat16 h1 = __float2bfloat16(v.y);
    __nv_bfloat16 h2 = __float2bfloat16(v.z);
    __nv_bfloat16 h3 = __float2bfloat16(v.w);
    __nv_bfloat16 l0 = __float2bfloat16(v.x - __bfloat162float(h0));
    __nv_bfloat16 l1 = __float2bfloat16(v.y - __bfloat162float(h1));
    __nv_bfloat16 l2 = __float2bfloat16(v.z - __bfloat162float(h2));
    __nv_bfloat16 l3 = __float2bfloat16(v.w - __bfloat162float(h3));
    __nv_bfloat162* hp = (__nv_bfloat162*)hi;
    __nv_bfloat162* lp = (__nv_bfloat162*)lo;
    hp[2 * i]     = __nv_bfloat162(h0, h1);
    hp[2 * i + 1] = __nv_bfloat162(h2, h3);
    lp[2 * i]     = __nv_bfloat162(l0, l1);
    lp[2 * i + 1] = __nv_bfloat162(l2, l3);
}

// ---------------------------------------------------------------------------
// bf16x3 mma.sync GEMM: C[m,n] = sum_k A[m,k]*B[n,k] + bias[n]
// A: [M][K] hi/lo bf16 row-major; B: [N][K] hi/lo bf16 row-major; C row-major.
// CTA 128x128, K-chunk 32, 8 warps (warp tile 32x64), 3-stage cp.async.
// ---------------------------------------------------------------------------
#define TILE_B2   8192                  // one 128x32 bf16 tile
#define STAGE_B2  (4 * TILE_B2)         // Ah, Al, Bh, Bl = 32 KB
#define NSTAGE    3
#define GEMM_DSMEM (NSTAGE * STAGE_B2 + 1024)
#define NCHUNK    (KDIM / 32)           // 64

// Swizzled byte offset within a 128x32 bf16 tile (64B rows, 4 x 16B chunks)
__device__ __forceinline__ uint32_t sw_off(int row, int chunk) {
    return (uint32_t)(row * 64) + ((uint32_t)(chunk ^ ((row >> 1) & 3)) << 4);
}

// Load one K-chunk (all four tiles) into stage at sbase.
__device__ __forceinline__ void load_stage(
    const __nv_bfloat16* __restrict__ Ah, const __nv_bfloat16* __restrict__ Al,
    const __nv_bfloat16* __restrict__ Bh, const __nv_bfloat16* __restrict__ Bl,
    int m0, int n0, int kc, uint32_t sbase, int tid)
{
    const int chunk = tid & 3;
    const int rbase = tid >> 2;          // 0..63
#pragma unroll
    for (int p = 0; p < 2; p++) {
        const int row = rbase + p * 64;
        const uint32_t so = sw_off(row, chunk);
        const size_t ga = (size_t)(m0 + row) * KDIM + kc + chunk * 8;
        const size_t gb = (size_t)(n0 + row) * KDIM + kc + chunk * 8;
        CP_ASYNC16(sbase + so,                 Ah + ga);
        CP_ASYNC16(sbase + TILE_B2 + so,       Al + ga);
        CP_ASYNC16(sbase + 2 * TILE_B2 + so,   Bh + gb);
        CP_ASYNC16(sbase + 3 * TILE_B2 + so,   Bl + gb);
    }
}

__global__ __launch_bounds__(256, 1)
void gemm_bf16x3(const __nv_bfloat16* __restrict__ Ah, const __nv_bfloat16* __restrict__ Al,
                 const __nv_bfloat16* __restrict__ Bh, const __nv_bfloat16* __restrict__ Bl,
                 const float* __restrict__ bias, float* __restrict__ C)
{
    extern __shared__ char dyn[];
    const int tid  = threadIdx.x;
    const int lane = tid & 31;
    const int w    = tid >> 5;
    const int m0   = blockIdx.y * 128;
    const int n0   = blockIdx.x * 128;
    const int wm   = (w & 3) * 32;       // warp m offset in tile
    const int wn   = (w >> 2) * 64;      // warp n offset in tile

    uint32_t base = (smem_u32(dyn) + 1023u) & ~1023u;

    // ldmatrix lane geometry
    const int r8   = lane & 7;
    const int mat  = lane >> 3;
    const int lrow = ((mat & 1) << 3) + r8;   // row within 16-row frag
    const int lch  = mat >> 1;                // k-chunk half (0/1)

    float acc[2][8][4];
#pragma unroll
    for (int i = 0; i < 2; i++)
#pragma unroll
        for (int j = 0; j < 8; j++)
#pragma unroll
            for (int c = 0; c < 4; c++) acc[i][j][c] = 0.0f;

    // Prologue: stages 0,1
    load_stage(Ah, Al, Bh, Bl, m0, n0, 0,  base,             tid); CP_COMMIT();
    load_stage(Ah, Al, Bh, Bl, m0, n0, 32, base + STAGE_B2,  tid); CP_COMMIT();

    for (int i = 0; i < NCHUNK; i++) {
        const uint32_t sb = base + (uint32_t)(i % NSTAGE) * STAGE_B2;
        CP_WAIT1();
        __syncthreads();

        const uint32_t sAh = sb, sAl = sb + TILE_B2;
        const uint32_t sBh = sb + 2 * TILE_B2, sBl = sb + 3 * TILE_B2;

#pragma unroll
        for (int ks = 0; ks < 2; ks++) {
            uint32_t ah[2][4], al[2][4], bh[4][4], bl[4][4];
#pragma unroll
            for (int mi = 0; mi < 2; mi++) {
                const int row = wm + mi * 16 + lrow;
                const uint32_t off = sw_off(row, ks * 2 + lch);
                LDSM4(ah[mi], sAh + off);
                LDSM4(al[mi], sAl + off);
            }
#pragma unroll
            for (int g = 0; g < 4; g++) {
                const int row = wn + g * 16 + lrow;
                const uint32_t off = sw_off(row, ks * 2 + lch);
                LDSM4(bh[g], sBh + off);
                LDSM4(bl[g], sBl + off);
            }
#pragma unroll
            for (int mi = 0; mi < 2; mi++)
#pragma unroll
                for (int g = 0; g < 4; g++)
#pragma unroll
                    for (int h = 0; h < 2; h++) {
                        float* d = acc[mi][g * 2 + h];
                        MMA16816(d, ah[mi], bh[g][h], bh[g][2 + h]);  // Ah*Bh
                        MMA16816(d, ah[mi], bl[g][h], bl[g][2 + h]);  // Ah*Bl
                        MMA16816(d, al[mi], bh[g][h], bh[g][2 + h]);  // Al*Bh
                    }
        }

        if (i + 2 < NCHUNK)
            load_stage(Ah, Al, Bh, Bl, m0, n0, (i + 2) * 32,
                       base + (uint32_t)((i + 2) % NSTAGE) * STAGE_B2, tid);
        CP_COMMIT();
    }

    // Epilogue: acc -> C (row-major) + bias
    const int qr = lane >> 2;            // 0..7
    const int qc = (lane & 3) * 2;       // 0,2,4,6
#pragma unroll
    for (int mi = 0; mi < 2; mi++) {
#pragma unroll
        for (int nj = 0; nj < 8; nj++) {
            const int col = n0 + wn + nj * 8 + qc;
            const float2 bb = *(const float2*)&bias[col];
            const int row0 = m0 + wm + mi * 16 + qr;
            float2 v0 = make_float2(acc[mi][nj][0] + bb.x, acc[mi][nj][1] + bb.y);
            float2 v1 = make_float2(acc[mi][nj][2] + bb.x, acc[mi][nj][3] + bb.y);
            *(float2*)&C[(size_t)row0 * EMB + col]       = v0;
            *(float2*)&C[(size_t)(row0 + 8) * EMB + col] = v1;
        }
    }
}

// ---------------------------------------------------------------------------
// Flash attention, fp32, causal. Q/K/V in [B,S,H,D] row-major (= [M][EMB]).
// One block = 64 queries of one (b,h).
// ---------------------------------------------------------------------------
#define QT_STR 68
#define VS_STR 132
#define PT_STR 65
#define FLASH_SMEM_FLOATS (128 * QT_STR * 2 + 64 * VS_STR + 64 * PT_STR)
#define FLASH_SMEM_BYTES  (FLASH_SMEM_FLOATS * 4)

__global__ __launch_bounds__(256, 1)
void flash_attn(const float* __restrict__ q, const float* __restrict__ k,
                const float* __restrict__ v)
{
    extern __shared__ float sm[];
    float* Qt = sm;                       // [128][68]
    float* Kt = Qt + 128 * QT_STR;        // [128][68]
    float* Vs = Kt + 128 * QT_STR;        // [64][132]
    float* Pt = Vs + 64 * VS_STR;         // [64][65]

    int tid = threadIdx.x;
    int w   = tid >> 5;
    int l   = tid & 31;
    int r8  = l >> 2;
    int dc4 = l & 3;
    int tx  = tid & 15;
    int ty  = tid >> 4;

    int q0 = blockIdx.x * 64;
    int bh = blockIdx.y;
    int b  = bh >> 4;
    int hh = bh & 15;
    size_t bbase = (size_t)b * SEQ * EMB + (size_t)hh * HEADD;
    const float* qp = q + bbase;
    const float* kp = k + bbase;
    const float* vp = v + bbase;

    const float scale = 0.08838834764831845f;  // 1/sqrt(128)

#pragma unroll
    for (int it = 0; it < 8; it++) {
        int row = it * 8 + r8;
        int dch = w * 4 + dc4;
        float4 val = *(const float4*)&qp[(size_t)(q0 + row) * EMB + dch * 4];
        Qt[(dch * 4 + 0) * QT_STR + row] = val.x * scale;
        Qt[(dch * 4 + 1) * QT_STR + row] = val.y * scale;
        Qt[(dch * 4 + 2) * QT_STR + row] = val.z * scale;
        Qt[(dch * 4 + 3) * QT_STR + row] = val.w * scale;
    }

    float acc[4][8];
#pragma unroll
    for (int i = 0; i < 4; i++)
#pragma unroll
        for (int j = 0; j < 8; j++) acc[i][j] = 0.0f;

    float m_run[4], l_run[4];
#pragma unroll
    for (int i = 0; i < 4; i++) { m_run[i] = -1e30f; l_run[i] = 0.0f; }

    int kb_end = blockIdx.x;
    for (int kb = 0; kb <= kb_end; kb++) {
        __syncthreads();

#pragma unroll
        for (int it = 0; it < 8; it++) {
            int row = it * 8 + r8;
            int dch = w * 4 + dc4;
            float4 val = *(const float4*)&kp[(size_t)(kb * 64 + row) * EMB + dch * 4];
            Kt[(dch * 4 + 0) * QT_STR + row] = val.x;
            Kt[(dch * 4 + 1) * QT_STR + row] = val.y;
            Kt[(dch * 4 + 2) * QT_STR + row] = val.z;
            Kt[(dch * 4 + 3) * QT_STR + row] = val.w;
        }
#pragma unroll
        for (int it = 0; it < 8; it++) {
            int idx = tid + it * 256;
            int row = idx >> 5;
            int c   = idx & 31;
            *(float4*)&Vs[row * VS_STR + c * 4] =
                *(const float4*)&vp[(size_t)(kb * 64 + row) * EMB + c * 4];
        }
        __syncthreads();

        float s[4][4];
#pragma unroll
        for (int i = 0; i < 4; i++)
#pragma unroll
            for (int j = 0; j < 4; j++) s[i][j] = 0.0f;

#pragma unroll 4
        for (int dd = 0; dd < 128; dd++) {
            float4 af = *(const float4*)&Qt[dd * QT_STR + ty * 4];
            float4 bf = *(const float4*)&Kt[dd * QT_STR + tx * 4];
            float av[4] = {af.x, af.y, af.z, af.w};
            float bv[4] = {bf.x, bf.y, bf.z, bf.w};
#pragma unroll
            for (int i = 0; i < 4; i++)
#pragma unroll
                for (int j = 0; j < 4; j++)
                    s[i][j] += av[i] * bv[j];
        }

        if (kb == kb_end) {
#pragma unroll
            for (int i = 0; i < 4; i++)
#pragma unroll
                for (int j = 0; j < 4; j++)
                    if (tx * 4 + j > ty * 4 + i) s[i][j] = -1e30f;
        }

        float alpha[4];
#pragma unroll
        for (int i = 0; i < 4; i++) {
            float mx = fmaxf(fmaxf(s[i][0], s[i][1]), fmaxf(s[i][2], s[i][3]));
#pragma unroll
            for (int o = 8; o > 0; o >>= 1)
                mx = fmaxf(mx, __shfl_xor_sync(0xffffffffu, mx, o));
            float mn = fmaxf(m_run[i], mx);
            alpha[i] = __expf(m_run[i] - mn);
            m_run[i] = mn;
            float rs = 0.0f;
#pragma unroll
            for (int j = 0; j < 4; j++) {
                s[i][j] = __expf(s[i][j] - mn);
                rs += s[i][j];
            }
#pragma unroll
            for (int o = 8; o > 0; o >>= 1)
                rs += __shfl_xor_sync(0xffffffffu, rs, o);
            l_run[i] = l_run[i] * alpha[i] + rs;
        }

#pragma unroll
        for (int i = 0; i < 4; i++)
#pragma unroll
            for (int j = 0; j < 8; j++) acc[i][j] *= alpha[i];

#pragma unroll
        for (int i = 0; i < 4; i++)
#pragma unroll
            for (int j = 0; j < 4; j++)
                Pt[(tx * 4 + j) * PT_STR + (ty * 4 + i)] = s[i][j];
        __syncthreads();

#pragma unroll 4
        for (int kk = 0; kk < 64; kk++) {
            float av[4];
#pragma unroll
            for (int i = 0; i < 4; i++) av[i] = Pt[kk * PT_STR + ty * 4 + i];
            float4 b0 = *(const float4*)&Vs[kk * VS_STR + tx * 8];
            float4 b1 = *(const float4*)&Vs[kk * VS_STR + tx * 8 + 4];
            float bv[8] = {b0.x, b0.y, b0.z, b0.w, b1.x, b1.y, b1.z, b1.w};
#pragma unroll
            for (int i = 0; i < 4; i++)
#pragma unroll
                for (int j = 0; j < 8; j++)
                    acc[i][j] += av[i] * bv[j];
        }
    }

    // ctx[b, s, h*128 + d] = O / l   (row-major [M][EMB])
#pragma unroll
    for (int i = 0; i < 4; i++) {
        float inv = 1.0f / l_run[i];
        int srow = q0 + ty * 4 + i;
        float* op = g_ctx + ((size_t)(b * SEQ + srow)) * EMB + hh * HEADD + tx * 8;
        *(float4*)(op)     = make_float4(acc[i][0] * inv, acc[i][1] * inv,
                                         acc[i][2] * inv, acc[i][3] * inv);
        *(float4*)(op + 4) = make_float4(acc[i][4] * inv, acc[i][5] * inv,
                                         acc[i][6] * inv, acc[i][7] * inv);
    }
}

// ---------------------------------------------------------------------------
extern "C" void kernel_launch(void* const* d_in, const int* in_sizes, int n_in,
                              void* d_out, int out_size)
{
    const float* x  = (const float*)d_in[0];
    const float* Wq = (const float*)d_in[2];
    const float* bq = (const float*)d_in[3];
    const float* Wk = (const float*)d_in[4];
    const float* bk = (const float*)d_in[5];
    const float* Wv = (const float*)d_in[6];
    const float* bv = (const float*)d_in[7];
    const float* Wo = (const float*)d_in[8];
    const float* bo = (const float*)d_in[9];
    float* out = (float*)d_out;

    __nv_bfloat16 *xh, *xl, *wh, *wl;
    float *qb, *kb, *vb, *cb;
    cudaGetSymbolAddress((void**)&xh, g_xh);
    cudaGetSymbolAddress((void**)&xl, g_xl);
    cudaGetSymbolAddress((void**)&wh, g_wh);
    cudaGetSymbolAddress((void**)&wl, g_wl);
    cudaGetSymbolAddress((void**)&qb, g_q);
    cudaGetSymbolAddress((void**)&kb, g_k);
    cudaGetSymbolAddress((void**)&vb, g_v);
    cudaGetSymbolAddress((void**)&cb, g_ctx);

    const float* Ws[4] = {Wq, Wk, Wv, Wo};

    const int nX4 = MROWS * EMB / 4;
    const int nW4 = EMB * EMB / 4;

    split_bf16<<<(nX4 + 255) / 256, 256>>>(x, xh, xl, nX4);
    for (int i = 0; i < 4; i++)
        split_bf16<<<(nW4 + 255) / 256, 256>>>(Ws[i], wh + (size_t)i * EMB * EMB,
                                               wl + (size_t)i * EMB * EMB, nW4);

    cudaFuncSetAttribute(gemm_bf16x3, cudaFuncAttributeMaxDynamicSharedMemorySize,
                         GEMM_DSMEM);
    dim3 gg(EMB / 128, MROWS / 128);  // (16, 64)

    gemm_bf16x3<<<gg, 256, GEMM_DSMEM>>>(xh, xl, wh + 0 * (size_t)EMB * EMB,
                                         wl + 0 * (size_t)EMB * EMB, bq, qb);
    gemm_bf16x3<<<gg, 256, GEMM_DSMEM>>>(xh, xl, wh + 1 * (size_t)EMB * EMB,
                                         wl + 1 * (size_t)EMB * EMB, bk, kb);
    gemm_bf16x3<<<gg, 256, GEMM_DSMEM>>>(xh, xl, wh + 2 * (size_t)EMB * EMB,
                                         wl + 2 * (size_t)EMB * EMB, bv, vb);

    cudaFuncSetAttribute(flash_attn, cudaFuncAttributeMaxDynamicSharedMemorySize,
                         FLASH_SMEM_BYTES);
    flash_attn<<<dim3(SEQ / 64, BATCH * HEADS), 256, FLASH_SMEM_BYTES>>>(qb, kb, vb);

    split_bf16<<<(nX4 + 255) / 256, 256>>>(cb, xh, xl, nX4);
    gemm_bf16x3<<<gg, 256, GEMM_DSMEM>>>(xh, xl, wh + 3 * (size_t)EMB * EMB,
                                         wl + 3 * (size_t)EMB * EMB, bo, out);
}

// round 4
// speedup vs baseline: 2.7329x; 1.6303x over previous
#include <cuda_runtime.h>
#include <cuda_bf16.h>
#include <math.h>
#include <cstdint>

// Problem constants
#define EMB    2048
#define HEADS  16
#define HEADD  128
#define BATCH  4
#define SEQ    2048
#define MROWS  (BATCH * SEQ)        // 8192
#define KDIM   EMB

// ---------------------------------------------------------------------------
// Scratch (device globals: allocation-free)
// ---------------------------------------------------------------------------
__device__ __nv_bfloat16 g_xh[(size_t)MROWS * EMB];   // X hi (reused as ctx hi)
__device__ __nv_bfloat16 g_xl[(size_t)MROWS * EMB];   // X lo (reused as ctx lo)
__device__ __nv_bfloat16 g_wh[4][(size_t)EMB * EMB];  // Wq,Wk,Wv,Wo hi
__device__ __nv_bfloat16 g_wl[4][(size_t)EMB * EMB];  // lo
__device__ __nv_bfloat16 g_qh[(size_t)MROWS * EMB];   // [B,S,H,D] row-major
__device__ __nv_bfloat16 g_ql[(size_t)MROWS * EMB];
__device__ __nv_bfloat16 g_kh[(size_t)MROWS * EMB];
__device__ __nv_bfloat16 g_kl[(size_t)MROWS * EMB];
__device__ __nv_bfloat16 g_vh[(size_t)MROWS * EMB];
__device__ __nv_bfloat16 g_vl[(size_t)MROWS * EMB];

// ---------------------------------------------------------------------------
// PTX helpers (compute_103-safe: no 'a' features)
// ---------------------------------------------------------------------------
__device__ __forceinline__ uint32_t smem_u32(const void* p) {
    uint32_t a;
    asm("{ .reg .u64 t; cvta.to.shared.u64 t, %1; cvt.u32.u64 %0, t; }" : "=r"(a) : "l"(p));
    return a;
}

#define CP_ASYNC16(dst, src) \
    asm volatile("cp.async.cg.shared.global [%0], [%1], 16;" :: "r"(dst), "l"(src) : "memory")
#define CP_COMMIT() asm volatile("cp.async.commit_group;" ::: "memory")
#define CP_WAIT1()  asm volatile("cp.async.wait_group 1;" ::: "memory")
#define CP_WAIT2()  asm volatile("cp.async.wait_group 2;" ::: "memory")

#define LDSM4(r, a)                                                              \
    asm volatile("ldmatrix.sync.aligned.m8n8.x4.shared.b16 {%0,%1,%2,%3}, [%4];" \
        : "=r"((r)[0]), "=r"((r)[1]), "=r"((r)[2]), "=r"((r)[3]) : "r"(a))

#define LDSM4T(r, a)                                                                   \
    asm volatile("ldmatrix.sync.aligned.m8n8.x4.trans.shared.b16 {%0,%1,%2,%3}, [%4];" \
        : "=r"((r)[0]), "=r"((r)[1]), "=r"((r)[2]), "=r"((r)[3]) : "r"(a))

#define MMA16816(d, a, b0, b1)                                                   \
    asm volatile("mma.sync.aligned.m16n8k16.row.col.f32.bf16.bf16.f32 "          \
        "{%0,%1,%2,%3}, {%4,%5,%6,%7}, {%8,%9}, {%0,%1,%2,%3};"                  \
        : "+f"((d)[0]), "+f"((d)[1]), "+f"((d)[2]), "+f"((d)[3])                  \
        : "r"((a)[0]), "r"((a)[1]), "r"((a)[2]), "r"((a)[3]), "r"(b0), "r"(b1))

// Swizzled byte offset within a [rows][32] bf16 tile (64B rows, 4 x 16B units)
__device__ __forceinline__ uint32_t sw_off(int row, int unit) {
    return (uint32_t)(row * 64) + ((uint32_t)(unit ^ ((row >> 1) & 3)) << 4);
}

__device__ __forceinline__ uint32_t pack_bf2(float lo, float hi) {
    __nv_bfloat162 t = __floats2bfloat162_rn(lo, hi);
    return *reinterpret_cast<uint32_t*>(&t);
}

// ---------------------------------------------------------------------------
// Split fp32 -> bf16 hi + bf16 lo  (vectorized x4)
// ---------------------------------------------------------------------------
__global__ void split_bf16(const float* __restrict__ in,
                           __nv_bfloat16* __restrict__ hi,
                           __nv_bfloat16* __restrict__ lo, int n4)
{
    int i = blockIdx.x * blockDim.x + threadIdx.x;
    if (i >= n4) return;
    float4 v = ((const float4*)in)[i];
    __nv_bfloat16 h0 = __float2bfloat16(v.x);
    __nv_bfloat16 h1 = __float2bfloat16(v.y);
    __nv_bfloat16 h2 = __float2bfloat16(v.z);
    __nv_bfloat16 h3 = __float2bfloat16(v.w);
    __nv_bfloat16 l0 = __float2bfloat16(v.x - __bfloat162float(h0));
    __nv_bfloat16 l1 = __float2bfloat16(v.y - __bfloat162float(h1));
    __nv_bfloat16 l2 = __float2bfloat16(v.z - __bfloat162float(h2));
    __nv_bfloat16 l3 = __float2bfloat16(v.w - __bfloat162float(h3));
    __nv_bfloat162* hp = (__nv_bfloat162*)hi;
    __nv_bfloat162* lp = (__nv_bfloat162*)lo;
    hp[2 * i]     = __nv_bfloat162(h0, h1);
    hp[2 * i + 1] = __nv_bfloat162(h2, h3);
    lp[2 * i]     = __nv_bfloat162(l0, l1);
    lp[2 * i + 1] = __nv_bfloat162(l2, l3);
}

// ---------------------------------------------------------------------------
// bf16x3 mma.sync GEMM: C[m,n] = sum_k A[m,k]*B[n,k] + bias[n]
// mode 0: C -> fp32 Cf row-major.  mode 1: C -> bf16 hi/lo (Ch, Cl).
// CTA 128x128, K-chunk 32, 8 warps (warp tile 32x64), 4-stage cp.async.
// ---------------------------------------------------------------------------
#define TILE_B2   8192                  // one 128x32 bf16 tile
#define STAGE_B2  (4 * TILE_B2)         // Ah, Al, Bh, Bl = 32 KB
#define NSTAGE    4
#define GEMM_DSMEM (NSTAGE * STAGE_B2 + 1024)
#define NCHUNK    (KDIM / 32)           // 64

__device__ __forceinline__ void load_stage(
    const __nv_bfloat16* __restrict__ Ah, const __nv_bfloat16* __restrict__ Al,
    const __nv_bfloat16* __restrict__ Bh, const __nv_bfloat16* __restrict__ Bl,
    int m0, int n0, int kc, uint32_t sbase, int tid)
{
    const int unit  = tid & 3;
    const int rbase = tid >> 2;          // 0..63
#pragma unroll
    for (int p = 0; p < 2; p++) {
        const int row = rbase + p * 64;
        const uint32_t so = sw_off(row, unit);
        const size_t ga = (size_t)(m0 + row) * KDIM + kc + unit * 8;
        const size_t gb = (size_t)(n0 + row) * KDIM + kc + unit * 8;
        CP_ASYNC16(sbase + so,                 Ah + ga);
        CP_ASYNC16(sbase + TILE_B2 + so,       Al + ga);
        CP_ASYNC16(sbase + 2 * TILE_B2 + so,   Bh + gb);
        CP_ASYNC16(sbase + 3 * TILE_B2 + so,   Bl + gb);
    }
}

__global__ __launch_bounds__(256, 1)
void gemm_bf16x3(const __nv_bfloat16* __restrict__ Ah, const __nv_bfloat16* __restrict__ Al,
                 const __nv_bfloat16* __restrict__ Bh, const __nv_bfloat16* __restrict__ Bl,
                 const float* __restrict__ bias, float* __restrict__ Cf,
                 __nv_bfloat16* __restrict__ Ch, __nv_bfloat16* __restrict__ Cl, int mode)
{
    extern __shared__ char dyn[];
    const int tid  = threadIdx.x;
    const int lane = tid & 31;
    const int w    = tid >> 5;
    const int m0   = blockIdx.y * 128;
    const int n0   = blockIdx.x * 128;
    const int wm   = (w & 3) * 32;
    const int wn   = (w >> 2) * 64;

    uint32_t base = (smem_u32(dyn) + 1023u) & ~1023u;

    const int r8   = lane & 7;
    const int mat  = lane >> 3;
    const int lrow = ((mat & 1) << 3) + r8;
    const int lch  = mat >> 1;

    float acc[2][8][4];
#pragma unroll
    for (int i = 0; i < 2; i++)
#pragma unroll
        for (int j = 0; j < 8; j++)
#pragma unroll
            for (int c = 0; c < 4; c++) acc[i][j][c] = 0.0f;

    load_stage(Ah, Al, Bh, Bl, m0, n0, 0,  base,                tid); CP_COMMIT();
    load_stage(Ah, Al, Bh, Bl, m0, n0, 32, base + STAGE_B2,     tid); CP_COMMIT();
    load_stage(Ah, Al, Bh, Bl, m0, n0, 64, base + 2 * STAGE_B2, tid); CP_COMMIT();

    for (int i = 0; i < NCHUNK; i++) {
        const uint32_t sb = base + (uint32_t)(i % NSTAGE) * STAGE_B2;
        CP_WAIT2();
        __syncthreads();
        if (i + 3 < NCHUNK)
            load_stage(Ah, Al, Bh, Bl, m0, n0, (i + 3) * 32,
                       base + (uint32_t)((i + 3) % NSTAGE) * STAGE_B2, tid);
        CP_COMMIT();

        const uint32_t sAh = sb, sAl = sb + TILE_B2;
        const uint32_t sBh = sb + 2 * TILE_B2, sBl = sb + 3 * TILE_B2;

#pragma unroll
        for (int ks = 0; ks < 2; ks++) {
            uint32_t ah[2][4], al[2][4], bh[4][4], bl[4][4];
#pragma unroll
            for (int mi = 0; mi < 2; mi++) {
                const uint32_t off = sw_off(wm + mi * 16 + lrow, ks * 2 + lch);
                LDSM4(ah[mi], sAh + off);
                LDSM4(al[mi], sAl + off);
            }
#pragma unroll
            for (int g = 0; g < 4; g++) {
                const uint32_t off = sw_off(wn + g * 16 + lrow, ks * 2 + lch);
                LDSM4(bh[g], sBh + off);
                LDSM4(bl[g], sBl + off);
            }
#pragma unroll
            for (int mi = 0; mi < 2; mi++)
#pragma unroll
                for (int g = 0; g < 4; g++)
#pragma unroll
                    for (int h = 0; h < 2; h++) {
                        float* d = acc[mi][g * 2 + h];
                        MMA16816(d, ah[mi], bh[g][h], bh[g][2 + h]);
                        MMA16816(d, ah[mi], bl[g][h], bl[g][2 + h]);
                        MMA16816(d, al[mi], bh[g][h], bh[g][2 + h]);
                    }
        }
    }

    // Epilogue
    const int qr = lane >> 2;
    const int qc = (lane & 3) * 2;
#pragma unroll
    for (int mi = 0; mi < 2; mi++) {
#pragma unroll
        for (int nj = 0; nj < 8; nj++) {
            const int col = n0 + wn + nj * 8 + qc;
            const float2 bb = *(const float2*)&bias[col];
            const int row0 = m0 + wm + mi * 16 + qr;
            float v00 = acc[mi][nj][0] + bb.x, v01 = acc[mi][nj][1] + bb.y;
            float v10 = acc[mi][nj][2] + bb.x, v11 = acc[mi][nj][3] + bb.y;
            if (mode == 0) {
                *(float2*)&Cf[(size_t)row0 * EMB + col]       = make_float2(v00, v01);
                *(float2*)&Cf[(size_t)(row0 + 8) * EMB + col] = make_float2(v10, v11);
            } else {
                __nv_bfloat162 h2 = __floats2bfloat162_rn(v00, v01);
                __nv_bfloat162 l2 = __floats2bfloat162_rn(v00 - __bfloat162float(h2.x),
                                                          v01 - __bfloat162float(h2.y));
                *(__nv_bfloat162*)(Ch + (size_t)row0 * EMB + col) = h2;
                *(__nv_bfloat162*)(Cl + (size_t)row0 * EMB + col) = l2;
                h2 = __floats2bfloat162_rn(v10, v11);
                l2 = __floats2bfloat162_rn(v10 - __bfloat162float(h2.x),
                                           v11 - __bfloat162float(h2.y));
                *(__nv_bfloat162*)(Ch + (size_t)(row0 + 8) * EMB + col) = h2;
                *(__nv_bfloat162*)(Cl + (size_t)(row0 + 8) * EMB + col) = l2;
            }
        }
    }
}

// ---------------------------------------------------------------------------
// Tensor-core flash attention, bf16x3, causal.
// Q-tile 128, KV-tile 64, 8 warps each owning a 16x64 score stripe.
// Q/K/V in [B,S,H,D] row-major bf16 hi/lo.  ctx out: bf16 hi/lo.
// ---------------------------------------------------------------------------
#define FL_SMEM (65536 + 2 * 65536)     // Q (hi+lo 64KB) + 2 KV buffers (64KB each)
#define FL_SCALE 0.08838834764831845f   // 1/sqrt(128)

__global__ __launch_bounds__(256, 1)
void flash_bf16(const __nv_bfloat16* __restrict__ qh, const __nv_bfloat16* __restrict__ ql,
                const __nv_bfloat16* __restrict__ kh, const __nv_bfloat16* __restrict__ kl,
                const __nv_bfloat16* __restrict__ vh, const __nv_bfloat16* __restrict__ vl,
                __nv_bfloat16* __restrict__ cth, __nv_bfloat16* __restrict__ ctl)
{
    extern __shared__ char smf[];
    const int tid  = threadIdx.x;
    const int lane = tid & 31;
    const int w    = tid >> 5;
    const int wm16 = w * 16;

    const int bx  = gridDim.x - 1 - blockIdx.x;   // heavy blocks first
    const int q0  = bx * 128;
    const int bh_ = blockIdx.y;
    const int bb  = bh_ >> 4;
    const int hh  = bh_ & 15;
    const int hcol = hh * 128;
    const int nkb = 2 * bx + 2;

    const uint32_t sQh = smem_u32(smf);
    const uint32_t sQl = sQh + 32768;
    const uint32_t sKV = sQh + 65536;     // buf b at sKV + b*65536: Kh,Kl,Vh,Vl (16KB each)

    // ldmatrix (non-trans) lane geometry
    const int r8   = lane & 7;
    const int mat  = lane >> 3;
    const int lrow = ((mat & 1) << 3) + r8;
    const int lch  = mat >> 1;
    // trans ldmatrix lane geometry (for V)
    const int tkrow = (lane & 7) + ((lane >> 4) << 3);
    const int tdh   = ((lane >> 3) & 1) << 3;
    // accum geometry
    const int t4 = lane & 3;
    const int gr = lane >> 2;

    // Prologue loads: Q (both halves) + KV block 0 -> group 0
    {
        const int unit = tid & 3;
        const int rr   = tid >> 2;       // 0..63
#pragma unroll
        for (int p = 0; p < 2; p++) {
            const int row = rr + p * 64;
            const size_t grow = (size_t)(bb * SEQ + q0 + row) * EMB + hcol + unit * 8;
#pragma unroll
            for (int c4 = 0; c4 < 4; c4++) {
                const uint32_t so = (uint32_t)c4 * 8192 + sw_off(row, unit);
                CP_ASYNC16(sQh + so, qh + grow + c4 * 32);
                CP_ASYNC16(sQl + so, ql + grow + c4 * 32);
            }
        }
        const size_t g0 = (size_t)(bb * SEQ + rr) * EMB + hcol + unit * 8;
#pragma unroll
        for (int c4 = 0; c4 < 4; c4++) {
            const uint32_t so = (uint32_t)c4 * 4096 + sw_off(rr, unit);
            CP_ASYNC16(sKV + so,         kh + g0 + c4 * 32);
            CP_ASYNC16(sKV + 16384 + so, kl + g0 + c4 * 32);
            CP_ASYNC16(sKV + 32768 + so, vh + g0 + c4 * 32);
            CP_ASYNC16(sKV + 49152 + so, vl + g0 + c4 * 32);
        }
        CP_COMMIT();
    }

    float o[16][4];
#pragma unroll
    for (int j = 0; j < 16; j++)
#pragma unroll
        for (int c = 0; c < 4; c++) o[j][c] = 0.0f;
    float m0 = -1e30f, m1 = -1e30f, l0 = 0.0f, l1 = 0.0f;

    for (int kb = 0; kb < nkb; kb++) {
        const uint32_t buf = sKV + (uint32_t)(kb & 1) * 65536;

        if (kb + 1 < nkb) {
            const uint32_t nbuf = sKV + (uint32_t)((kb + 1) & 1) * 65536;
            const int unit = tid & 3;
            const int rr   = tid >> 2;
            const size_t grow = (size_t)(bb * SEQ + (kb + 1) * 64 + rr) * EMB + hcol + unit * 8;
#pragma unroll
            for (int c4 = 0; c4 < 4; c4++) {
                const uint32_t so = (uint32_t)c4 * 4096 + sw_off(rr, unit);
                CP_ASYNC16(nbuf + so,         kh + grow + c4 * 32);
                CP_ASYNC16(nbuf + 16384 + so, kl + grow + c4 * 32);
                CP_ASYNC16(nbuf + 32768 + so, vh + grow + c4 * 32);
                CP_ASYNC16(nbuf + 49152 + so, vl + grow + c4 * 32);
            }
        }
        CP_COMMIT();
        CP_WAIT1();
        __syncthreads();

        if (kb * 64 <= q0 + wm16 + 15) {       // not fully masked for this warp
            float s[8][4];
#pragma unroll
            for (int j = 0; j < 8; j++)
#pragma unroll
                for (int c = 0; c < 4; c++) s[j][c] = 0.0f;

            // ---- S = Q K^T (bf16x3) ----
#pragma unroll
            for (int ks = 0; ks < 8; ks++) {
                const uint32_t qoff = (uint32_t)(ks >> 1) * 8192 +
                                      sw_off(wm16 + lrow, (ks & 1) * 2 + lch);
                uint32_t qa_h[4], qa_l[4];
                LDSM4(qa_h, sQh + qoff);
                LDSM4(qa_l, sQl + qoff);
#pragma unroll
                for (int g = 0; g < 4; g++) {
                    const uint32_t koff = (uint32_t)(ks >> 1) * 4096 +
                                          sw_off(g * 16 + lrow, (ks & 1) * 2 + lch);
                    uint32_t kbh[4], kbl[4];
                    LDSM4(kbh, buf + koff);
                    LDSM4(kbl, buf + 16384 + koff);
#pragma unroll
                    for (int h = 0; h < 2; h++) {
                        float* d = s[g * 2 + h];
                        MMA16816(d, qa_h, kbh[h], kbh[2 + h]);
                        MMA16816(d, qa_h, kbl[h], kbl[2 + h]);
                        MMA16816(d, qa_l, kbh[h], kbh[2 + h]);
                    }
                }
            }

            // scale + causal mask
#pragma unroll
            for (int j = 0; j < 8; j++)
#pragma unroll
                for (int c = 0; c < 4; c++) s[j][c] *= FL_SCALE;

            if (kb * 64 + 63 > q0 + wm16) {
                const int row0 = q0 + wm16 + gr;
#pragma unroll
                for (int j = 0; j < 8; j++) {
                    const int col = kb * 64 + (j >> 1) * 16 + (j & 1) * 8 + 2 * t4;
                    if (col > row0)         s[j][0] = -1e30f;
                    if (col + 1 > row0)     s[j][1] = -1e30f;
                    if (col > row0 + 8)     s[j][2] = -1e30f;
                    if (col + 1 > row0 + 8) s[j][3] = -1e30f;
                }
            }

            // ---- online softmax (rows gr, gr+8) ----
            float mx0 = -1e30f, mx1 = -1e30f;
#pragma unroll
            for (int j = 0; j < 8; j++) {
                mx0 = fmaxf(mx0, fmaxf(s[j][0], s[j][1]));
                mx1 = fmaxf(mx1, fmaxf(s[j][2], s[j][3]));
            }
            mx0 = fmaxf(mx0, __shfl_xor_sync(0xffffffffu, mx0, 1));
            mx0 = fmaxf(mx0, __shfl_xor_sync(0xffffffffu, mx0, 2));
            mx1 = fmaxf(mx1, __shfl_xor_sync(0xffffffffu, mx1, 1));
            mx1 = fmaxf(mx1, __shfl_xor_sync(0xffffffffu, mx1, 2));

            const float mn0 = fmaxf(m0, mx0), mn1 = fmaxf(m1, mx1);
            const float a0 = __expf(m0 - mn0), a1 = __expf(m1 - mn1);
            m0 = mn0; m1 = mn1;

            float rs0 = 0.0f, rs1 = 0.0f;
#pragma unroll
            for (int j = 0; j < 8; j++) {
                s[j][0] = __expf(s[j][0] - mn0); rs0 += s[j][0];
                s[j][1] = __expf(s[j][1] - mn0); rs0 += s[j][1];
                s[j][2] = __expf(s[j][2] - mn1); rs1 += s[j][2];
                s[j][3] = __expf(s[j][3] - mn1); rs1 += s[j][3];
            }
            rs0 += __shfl_xor_sync(0xffffffffu, rs0, 1);
            rs0 += __shfl_xor_sync(0xffffffffu, rs0, 2);
            rs1 += __shfl_xor_sync(0xffffffffu, rs1, 1);
            rs1 += __shfl_xor_sync(0xffffffffu, rs1, 2);
            l0 = l0 * a0 + rs0;
            l1 = l1 * a1 + rs1;

#pragma unroll
            for (int j = 0; j < 16; j++) {
                o[j][0] *= a0; o[j][1] *= a0;
                o[j][2] *= a1; o[j][3] *= a1;
            }

            // ---- O += P V (bf16x3), P from accum regs ----
#pragma unroll
            for (int kk = 0; kk < 4; kk++) {
                const float* sA = s[2 * kk];
                const float* sB = s[2 * kk + 1];
                uint32_t pa_h[4], pa_l[4];
                {
                    __nv_bfloat162 h;
                    h = __floats2bfloat162_rn(sA[0], sA[1]);
                    pa_h[0] = *reinterpret_cast<uint32_t*>(&h);
                    pa_l[0] = pack_bf2(sA[0] - __bfloat162float(h.x), sA[1] - __bfloat162float(h.y));
                    h = __floats2bfloat162_rn(sA[2], sA[3]);
                    pa_h[1] = *reinterpret_cast<uint32_t*>(&h);
                    pa_l[1] = pack_bf2(sA[2] - __bfloat162float(h.x), sA[3] - __bfloat162float(h.y));
                    h = __floats2bfloat162_rn(sB[0], sB[1]);
                    pa_h[2] = *reinterpret_cast<uint32_t*>(&h);
                    pa_l[2] = pack_bf2(sB[0] - __bfloat162float(h.x), sB[1] - __bfloat162float(h.y));
                    h = __floats2bfloat162_rn(sB[2], sB[3]);
                    pa_h[3] = *reinterpret_cast<uint32_t*>(&h);
                    pa_l[3] = pack_bf2(sB[2] - __bfloat162float(h.x), sB[3] - __bfloat162float(h.y));
                }
                const int vkrow = kk * 16 + tkrow;
#pragma unroll
                for (int gn = 0; gn < 8; gn++) {
                    const int dcol = gn * 16 + tdh;
                    const uint32_t voff = (uint32_t)(dcol >> 5) * 4096 +
                                          sw_off(vkrow, (dcol >> 3) & 3);
                    uint32_t vbh[4], vbl[4];
                    LDSM4T(vbh, buf + 32768 + voff);
                    LDSM4T(vbl, buf + 49152 + voff);
#pragma unroll
                    for (int h = 0; h < 2; h++) {
                        float* d = o[gn * 2 + h];
                        MMA16816(d, pa_h, vbh[h], vbh[2 + h]);
                        MMA16816(d, pa_l, vbh[h], vbh[2 + h]);
                        MMA16816(d, pa_h, vbl[h], vbl[2 + h]);
                    }
                }
            }
        }
        __syncthreads();
    }

    // Epilogue: ctx = O / l, split to bf16 hi/lo, [B,S,E] row-major
    const float inv0 = 1.0f / l0, inv1 = 1.0f / l1;
    const int row0 = q0 + wm16 + gr;
    const size_t base0 = (size_t)(bb * SEQ + row0) * EMB + hcol;
    const size_t base1 = base0 + (size_t)8 * EMB;
#pragma unroll
    for (int j = 0; j < 16; j++) {
        const int d0 = j * 8 + 2 * t4;
        float v0 = o[j][0] * inv0, v1 = o[j][1] * inv0;
        __nv_bfloat162 h2 = __floats2bfloat162_rn(v0, v1);
        __nv_bfloat162 l2 = __floats2bfloat162_rn(v0 - __bfloat162float(h2.x),
                                                  v1 - __bfloat162float(h2.y));
        *(__nv_bfloat162*)(cth + base0 + d0) = h2;
        *(__nv_bfloat162*)(ctl + base0 + d0) = l2;
        float v2 = o[j][2] * inv1, v3 = o[j][3] * inv1;
        h2 = __floats2bfloat162_rn(v2, v3);
        l2 = __floats2bfloat162_rn(v2 - __bfloat162float(h2.x),
                                   v3 - __bfloat162float(h2.y));
        *(__nv_bfloat162*)(cth + base1 + d0) = h2;
        *(__nv_bfloat162*)(ctl + base1 + d0) = l2;
    }
}

// ---------------------------------------------------------------------------
extern "C" void kernel_launch(void* const* d_in, const int* in_sizes, int n_in,
                              void* d_out, int out_size)
{
    const float* x  = (const float*)d_in[0];
    const float* Wq = (const float*)d_in[2];
    const float* bq = (const float*)d_in[3];
    const float* Wk = (const float*)d_in[4];
    const float* bk = (const float*)d_in[5];
    const float* Wv = (const float*)d_in[6];
    const float* bv = (const float*)d_in[7];
    const float* Wo = (const float*)d_in[8];
    const float* bo = (const float*)d_in[9];
    float* out = (float*)d_out;

    __nv_bfloat16 *xh, *xl, *wh, *wl, *qh, *ql, *kh, *kl, *vh, *vl;
    cudaGetSymbolAddress((void**)&xh, g_xh);
    cudaGetSymbolAddress((void**)&xl, g_xl);
    cudaGetSymbolAddress((void**)&wh, g_wh);
    cudaGetSymbolAddress((void**)&wl, g_wl);
    cudaGetSymbolAddress((void**)&qh, g_qh);
    cudaGetSymbolAddress((void**)&ql, g_ql);
    cudaGetSymbolAddress((void**)&kh, g_kh);
    cudaGetSymbolAddress((void**)&kl, g_kl);
    cudaGetSymbolAddress((void**)&vh, g_vh);
    cudaGetSymbolAddress((void**)&vl, g_vl);

    const float* Ws[4] = {Wq, Wk, Wv, Wo};
    const int nX4 = MROWS * EMB / 4;
    const int nW4 = EMB * EMB / 4;

    split_bf16<<<(nX4 + 255) / 256, 256>>>(x, xh, xl, nX4);
    for (int i = 0; i < 4; i++)
        split_bf16<<<(nW4 + 255) / 256, 256>>>(Ws[i], wh + (size_t)i * EMB * EMB,
                                               wl + (size_t)i * EMB * EMB, nW4);

    cudaFuncSetAttribute(gemm_bf16x3, cudaFuncAttributeMaxDynamicSharedMemorySize,
                         GEMM_DSMEM);
    dim3 gg(EMB / 128, MROWS / 128);  // (16, 64)

    gemm_bf16x3<<<gg, 256, GEMM_DSMEM>>>(xh, xl, wh + 0 * (size_t)EMB * EMB,
                                         wl + 0 * (size_t)EMB * EMB, bq,
                                         nullptr, qh, ql, 1);
    gemm_bf16x3<<<gg, 256, GEMM_DSMEM>>>(xh, xl, wh + 1 * (size_t)EMB * EMB,
                                         wl + 1 * (size_t)EMB * EMB, bk,
                                         nullptr, kh, kl, 1);
    gemm_bf16x3<<<gg, 256, GEMM_DSMEM>>>(xh, xl, wh + 2 * (size_t)EMB * EMB,
                                         wl + 2 * (size_t)EMB * EMB, bv,
                                         nullptr, vh, vl, 1);

    cudaFuncSetAttribute(flash_bf16, cudaFuncAttributeMaxDynamicSharedMemorySize,
                         FL_SMEM);
    // flash writes ctx into xh/xl (X is dead after the QKV GEMMs)
    flash_bf16<<<dim3(SEQ / 128, BATCH * HEADS), 256, FL_SMEM>>>(qh, ql, kh, kl, vh, vl,
                                                                 xh, xl);

    gemm_bf16x3<<<gg, 256, GEMM_DSMEM>>>(xh, xl, wh + 3 * (size_t)EMB * EMB,
                                         wl + 3 * (size_t)EMB * EMB, bo,
                                         out, nullptr, nullptr, 0);
}

// round 5
// speedup vs baseline: 4.2945x; 1.5714x over previous
#include <cuda_runtime.h>
#include <cuda_fp16.h>
#include <math.h>
#include <cstdint>

// Problem constants
#define EMB    2048
#define HEADS  16
#define HEADD  128
#define BATCH  4
#define SEQ    2048
#define MROWS  (BATCH * SEQ)        // 8192
#define KDIM   EMB

// ---------------------------------------------------------------------------
// Scratch (device globals: allocation-free)
// ---------------------------------------------------------------------------
__device__ __half g_xh[(size_t)MROWS * EMB];   // X hi (reused as ctx hi)
__device__ __half g_xl[(size_t)MROWS * EMB];   // X lo (reused as ctx lo)
__device__ __half g_w[4][(size_t)EMB * EMB];   // Wq,Wk,Wv,Wo (fp16, hi only)
__device__ __half g_qh[(size_t)MROWS * EMB];   // [B,S,H,D] row-major
__device__ __half g_ql[(size_t)MROWS * EMB];
__device__ __half g_kh[(size_t)MROWS * EMB];
__device__ __half g_vh[(size_t)MROWS * EMB];

// ---------------------------------------------------------------------------
// PTX helpers (compute_103-safe: no 'a' features)
// ---------------------------------------------------------------------------
__device__ __forceinline__ uint32_t smem_u32(const void* p) {
    uint32_t a;
    asm("{ .reg .u64 t; cvta.to.shared.u64 t, %1; cvt.u32.u64 %0, t; }" : "=r"(a) : "l"(p));
    return a;
}

#define CP_ASYNC16(dst, src) \
    asm volatile("cp.async.cg.shared.global [%0], [%1], 16;" :: "r"(dst), "l"(src) : "memory")
#define CP_COMMIT() asm volatile("cp.async.commit_group;" ::: "memory")
#define CP_WAIT1()  asm volatile("cp.async.wait_group 1;" ::: "memory")
#define CP_WAIT2()  asm volatile("cp.async.wait_group 2;" ::: "memory")

#define LDSM4(r, a)                                                              \
    asm volatile("ldmatrix.sync.aligned.m8n8.x4.shared.b16 {%0,%1,%2,%3}, [%4];" \
        : "=r"((r)[0]), "=r"((r)[1]), "=r"((r)[2]), "=r"((r)[3]) : "r"(a))

#define LDSM4T(r, a)                                                                   \
    asm volatile("ldmatrix.sync.aligned.m8n8.x4.trans.shared.b16 {%0,%1,%2,%3}, [%4];" \
        : "=r"((r)[0]), "=r"((r)[1]), "=r"((r)[2]), "=r"((r)[3]) : "r"(a))

#define MMA16816(d, a, b0, b1)                                                   \
    asm volatile("mma.sync.aligned.m16n8k16.row.col.f32.f16.f16.f32 "            \
        "{%0,%1,%2,%3}, {%4,%5,%6,%7}, {%8,%9}, {%0,%1,%2,%3};"                  \
        : "+f"((d)[0]), "+f"((d)[1]), "+f"((d)[2]), "+f"((d)[3])                  \
        : "r"((a)[0]), "r"((a)[1]), "r"((a)[2]), "r"((a)[3]), "r"(b0), "r"(b1))

// Swizzled byte offset within a [rows][32] fp16 tile (64B rows, 4 x 16B units)
__device__ __forceinline__ uint32_t sw_off(int row, int unit) {
    return (uint32_t)(row * 64) + ((uint32_t)(unit ^ ((row >> 1) & 3)) << 4);
}

__device__ __forceinline__ uint32_t pack_h2(float a, float b) {
    __half2 t = __floats2half2_rn(a, b);
    return *reinterpret_cast<uint32_t*>(&t);
}

// ---------------------------------------------------------------------------
// Split fp32 -> fp16 hi + fp16 lo  (vectorized x4)
// ---------------------------------------------------------------------------
__global__ void split_f16(const float* __restrict__ in,
                          __half* __restrict__ hi,
                          __half* __restrict__ lo, int n4)
{
    int i = blockIdx.x * blockDim.x + threadIdx.x;
    if (i >= n4) return;
    float4 v = ((const float4*)in)[i];
    __half h0 = __float2half_rn(v.x);
    __half h1 = __float2half_rn(v.y);
    __half h2 = __float2half_rn(v.z);
    __half h3 = __float2half_rn(v.w);
    __half2* hp = (__half2*)hi;
    __half2* lp = (__half2*)lo;
    hp[2 * i]     = __half2(h0, h1);
    hp[2 * i + 1] = __half2(h2, h3);
    lp[2 * i]     = __floats2half2_rn(v.x - __half2float(h0), v.y - __half2float(h1));
    lp[2 * i + 1] = __floats2half2_rn(v.z - __half2float(h2), v.w - __half2float(h3));
}

// fp32 -> fp16 (hi only), for weights
__global__ void conv_f16(const float* __restrict__ in, __half* __restrict__ hi, int n4)
{
    int i = blockIdx.x * blockDim.x + threadIdx.x;
    if (i >= n4) return;
    float4 v = ((const float4*)in)[i];
    __half2* hp = (__half2*)hi;
    hp[2 * i]     = __floats2half2_rn(v.x, v.y);
    hp[2 * i + 1] = __floats2half2_rn(v.z, v.w);
}

// ---------------------------------------------------------------------------
// fp16x2 mma.sync GEMM: C[m,n] = (sum_k (Ah+Al)[m,k]*B[n,k] + bias[n]) * scale
// mode 0: -> fp32 Cf.   mode 1: -> fp16 hi/lo (Ch, Cl).   mode 2: -> fp16 Ch.
// CTA 128x128, K-chunk 32, 8 warps (warp tile 32x64), 4-stage cp.async.
// ---------------------------------------------------------------------------
#define TILE_B2   8192                  // one 128x32 fp16 tile
#define STAGE_B2  (3 * TILE_B2)         // Ah, Al, Bh = 24 KB
#define NSTAGE    4
#define GEMM_DSMEM (NSTAGE * STAGE_B2 + 1024)
#define NCHUNK    (KDIM / 32)           // 64

__device__ __forceinline__ void load_stage(
    const __half* __restrict__ Ah, const __half* __restrict__ Al,
    const __half* __restrict__ Bh,
    int m0, int n0, int kc, uint32_t sbase, int tid)
{
    const int unit  = tid & 3;
    const int rbase = tid >> 2;          // 0..63
#pragma unroll
    for (int p = 0; p < 2; p++) {
        const int row = rbase + p * 64;
        const uint32_t so = sw_off(row, unit);
        const size_t ga = (size_t)(m0 + row) * KDIM + kc + unit * 8;
        const size_t gb = (size_t)(n0 + row) * KDIM + kc + unit * 8;
        CP_ASYNC16(sbase + so,               Ah + ga);
        CP_ASYNC16(sbase + TILE_B2 + so,     Al + ga);
        CP_ASYNC16(sbase + 2 * TILE_B2 + so, Bh + gb);
    }
}

__global__ __launch_bounds__(256, 1)
void gemm_f16x2(const __half* __restrict__ Ah, const __half* __restrict__ Al,
                const __half* __restrict__ Bh,
                const float* __restrict__ bias, float* __restrict__ Cf,
                __half* __restrict__ Ch, __half* __restrict__ Cl,
                int mode, float scale)
{
    extern __shared__ char dyn[];
    const int tid  = threadIdx.x;
    const int lane = tid & 31;
    const int w    = tid >> 5;
    const int m0   = blockIdx.y * 128;
    const int n0   = blockIdx.x * 128;
    const int wm   = (w & 3) * 32;
    const int wn   = (w >> 2) * 64;

    uint32_t base = (smem_u32(dyn) + 1023u) & ~1023u;

    const int r8   = lane & 7;
    const int mat  = lane >> 3;
    const int lrow = ((mat & 1) << 3) + r8;
    const int lch  = mat >> 1;

    float acc[2][8][4];
#pragma unroll
    for (int i = 0; i < 2; i++)
#pragma unroll
        for (int j = 0; j < 8; j++)
#pragma unroll
            for (int c = 0; c < 4; c++) acc[i][j][c] = 0.0f;

    load_stage(Ah, Al, Bh, m0, n0, 0,  base,                tid); CP_COMMIT();
    load_stage(Ah, Al, Bh, m0, n0, 32, base + STAGE_B2,     tid); CP_COMMIT();
    load_stage(Ah, Al, Bh, m0, n0, 64, base + 2 * STAGE_B2, tid); CP_COMMIT();

    for (int i = 0; i < NCHUNK; i++) {
        const uint32_t sb = base + (uint32_t)(i % NSTAGE) * STAGE_B2;
        CP_WAIT2();
        __syncthreads();
        if (i + 3 < NCHUNK)
            load_stage(Ah, Al, Bh, m0, n0, (i + 3) * 32,
                       base + (uint32_t)((i + 3) % NSTAGE) * STAGE_B2, tid);
        CP_COMMIT();

        const uint32_t sAh = sb, sAl = sb + TILE_B2, sBh = sb + 2 * TILE_B2;

#pragma unroll
        for (int ks = 0; ks < 2; ks++) {
            uint32_t ah[2][4], al[2][4], bh[4][4];
#pragma unroll
            for (int mi = 0; mi < 2; mi++) {
                const uint32_t off = sw_off(wm + mi * 16 + lrow, ks * 2 + lch);
                LDSM4(ah[mi], sAh + off);
                LDSM4(al[mi], sAl + off);
            }
#pragma unroll
            for (int g = 0; g < 4; g++) {
                const uint32_t off = sw_off(wn + g * 16 + lrow, ks * 2 + lch);
                LDSM4(bh[g], sBh + off);
            }
#pragma unroll
            for (int mi = 0; mi < 2; mi++)
#pragma unroll
                for (int g = 0; g < 4; g++)
#pragma unroll
                    for (int h = 0; h < 2; h++) {
                        float* d = acc[mi][g * 2 + h];
                        MMA16816(d, ah[mi], bh[g][h], bh[g][2 + h]);
                        MMA16816(d, al[mi], bh[g][h], bh[g][2 + h]);
                    }
        }
    }

    // Epilogue
    const int qr = lane >> 2;
    const int qc = (lane & 3) * 2;
#pragma unroll
    for (int mi = 0; mi < 2; mi++) {
#pragma unroll
        for (int nj = 0; nj < 8; nj++) {
            const int col = n0 + wn + nj * 8 + qc;
            const float2 bb = *(const float2*)&bias[col];
            const int row0 = m0 + wm + mi * 16 + qr;
            float v00 = (acc[mi][nj][0] + bb.x) * scale;
            float v01 = (acc[mi][nj][1] + bb.y) * scale;
            float v10 = (acc[mi][nj][2] + bb.x) * scale;
            float v11 = (acc[mi][nj][3] + bb.y) * scale;
            if (mode == 0) {
                *(float2*)&Cf[(size_t)row0 * EMB + col]       = make_float2(v00, v01);
                *(float2*)&Cf[(size_t)(row0 + 8) * EMB + col] = make_float2(v10, v11);
            } else if (mode == 1) {
                __half2 h2 = __floats2half2_rn(v00, v01);
                *(__half2*)(Ch + (size_t)row0 * EMB + col) = h2;
                *(__half2*)(Cl + (size_t)row0 * EMB + col) =
                    __floats2half2_rn(v00 - __half2float(h2.x), v01 - __half2float(h2.y));
                h2 = __floats2half2_rn(v10, v11);
                *(__half2*)(Ch + (size_t)(row0 + 8) * EMB + col) = h2;
                *(__half2*)(Cl + (size_t)(row0 + 8) * EMB + col) =
                    __floats2half2_rn(v10 - __half2float(h2.x), v11 - __half2float(h2.y));
            } else {
                *(__half2*)(Ch + (size_t)row0 * EMB + col)       = __floats2half2_rn(v00, v01);
                *(__half2*)(Ch + (size_t)(row0 + 8) * EMB + col) = __floats2half2_rn(v10, v11);
            }
        }
    }
}

// ---------------------------------------------------------------------------
// Tensor-core flash attention, fp16x2, causal. 1/sqrt(d) pre-folded into Q.
// Q-tile 128, KV-tile 64, 8 warps each owning a 16x64 score stripe.
// Q split hi/lo; K,V single fp16. ctx out: fp16 hi/lo.
// ---------------------------------------------------------------------------
#define FL_SMEM (65536 + 2 * 32768)     // Q (hi+lo 64KB) + 2 KV buffers (32KB each)

__global__ __launch_bounds__(256, 1)
void flash_f16(const __half* __restrict__ qh, const __half* __restrict__ ql,
               const __half* __restrict__ kh, const __half* __restrict__ vh,
               __half* __restrict__ cth, __half* __restrict__ ctl)
{
    extern __shared__ char smf[];
    const int tid  = threadIdx.x;
    const int lane = tid & 31;
    const int w    = tid >> 5;
    const int wm16 = w * 16;

    const int bx  = gridDim.x - 1 - blockIdx.x;   // heavy blocks first
    const int q0  = bx * 128;
    const int bh_ = blockIdx.y;
    const int bb  = bh_ >> 4;
    const int hh  = bh_ & 15;
    const int hcol = hh * 128;
    const int nkb = 2 * bx + 2;

    const uint32_t sQh = smem_u32(smf);
    const uint32_t sQl = sQh + 32768;
    const uint32_t sKV = sQh + 65536;     // buf b at sKV + b*32768: Kh, Vh (16KB each)

    const int r8   = lane & 7;
    const int mat  = lane >> 3;
    const int lrow = ((mat & 1) << 3) + r8;
    const int lch  = mat >> 1;
    const int tkrow = (lane & 7) + ((lane >> 4) << 3);
    const int tdh   = ((lane >> 3) & 1) << 3;
    const int t4 = lane & 3;
    const int gr = lane >> 2;

    // Prologue: Q (hi+lo) + KV block 0
    {
        const int unit = tid & 3;
        const int rr   = tid >> 2;       // 0..63
#pragma unroll
        for (int p = 0; p < 2; p++) {
            const int row = rr + p * 64;
            const size_t grow = (size_t)(bb * SEQ + q0 + row) * EMB + hcol + unit * 8;
#pragma unroll
            for (int c4 = 0; c4 < 4; c4++) {
                const uint32_t so = (uint32_t)c4 * 8192 + sw_off(row, unit);
                CP_ASYNC16(sQh + so, qh + grow + c4 * 32);
                CP_ASYNC16(sQl + so, ql + grow + c4 * 32);
            }
        }
        const size_t g0 = (size_t)(bb * SEQ + rr) * EMB + hcol + unit * 8;
#pragma unroll
        for (int c4 = 0; c4 < 4; c4++) {
            const uint32_t so = (uint32_t)c4 * 4096 + sw_off(rr, unit);
            CP_ASYNC16(sKV + so,         kh + g0 + c4 * 32);
            CP_ASYNC16(sKV + 16384 + so, vh + g0 + c4 * 32);
        }
        CP_COMMIT();
    }

    float o[16][4];
#pragma unroll
    for (int j = 0; j < 16; j++)
#pragma unroll
        for (int c = 0; c < 4; c++) o[j][c] = 0.0f;
    float m0 = -1e30f, m1 = -1e30f, l0 = 0.0f, l1 = 0.0f;

    for (int kb = 0; kb < nkb; kb++) {
        const uint32_t buf = sKV + (uint32_t)(kb & 1) * 32768;

        if (kb + 1 < nkb) {
            const uint32_t nbuf = sKV + (uint32_t)((kb + 1) & 1) * 32768;
            const int unit = tid & 3;
            const int rr   = tid >> 2;
            const size_t grow = (size_t)(bb * SEQ + (kb + 1) * 64 + rr) * EMB + hcol + unit * 8;
#pragma unroll
            for (int c4 = 0; c4 < 4; c4++) {
                const uint32_t so = (uint32_t)c4 * 4096 + sw_off(rr, unit);
                CP_ASYNC16(nbuf + so,         kh + grow + c4 * 32);
                CP_ASYNC16(nbuf + 16384 + so, vh + grow + c4 * 32);
            }
        }
        CP_COMMIT();
        CP_WAIT1();
        __syncthreads();

        if (kb * 64 <= q0 + wm16 + 15) {
            float s[8][4];
#pragma unroll
            for (int j = 0; j < 8; j++)
#pragma unroll
                for (int c = 0; c < 4; c++) s[j][c] = 0.0f;

            // ---- S = Q K^T (fp16x2: qh + ql, single kh) ----
#pragma unroll
            for (int ks = 0; ks < 8; ks++) {
                const uint32_t qoff = (uint32_t)(ks >> 1) * 8192 +
                                      sw_off(wm16 + lrow, (ks & 1) * 2 + lch);
                uint32_t qa_h[4], qa_l[4];
                LDSM4(qa_h, sQh + qoff);
                LDSM4(qa_l, sQl + qoff);
#pragma unroll
                for (int g = 0; g < 4; g++) {
                    const uint32_t koff = (uint32_t)(ks >> 1) * 4096 +
                                          sw_off(g * 16 + lrow, (ks & 1) * 2 + lch);
                    uint32_t kbh[4];
                    LDSM4(kbh, buf + koff);
#pragma unroll
                    for (int h = 0; h < 2; h++) {
                        float* d = s[g * 2 + h];
                        MMA16816(d, qa_h, kbh[h], kbh[2 + h]);
                        MMA16816(d, qa_l, kbh[h], kbh[2 + h]);
                    }
                }
            }

            // causal mask (scale already folded into Q)
            if (kb * 64 + 63 > q0 + wm16) {
                const int row0 = q0 + wm16 + gr;
#pragma unroll
                for (int j = 0; j < 8; j++) {
                    const int col = kb * 64 + (j >> 1) * 16 + (j & 1) * 8 + 2 * t4;
                    if (col > row0)         s[j][0] = -1e30f;
                    if (col + 1 > row0)     s[j][1] = -1e30f;
                    if (col > row0 + 8)     s[j][2] = -1e30f;
                    if (col + 1 > row0 + 8) s[j][3] = -1e30f;
                }
            }

            // ---- online softmax ----
            float mx0 = -1e30f, mx1 = -1e30f;
#pragma unroll
            for (int j = 0; j < 8; j++) {
                mx0 = fmaxf(mx0, fmaxf(s[j][0], s[j][1]));
                mx1 = fmaxf(mx1, fmaxf(s[j][2], s[j][3]));
            }
            mx0 = fmaxf(mx0, __shfl_xor_sync(0xffffffffu, mx0, 1));
            mx0 = fmaxf(mx0, __shfl_xor_sync(0xffffffffu, mx0, 2));
            mx1 = fmaxf(mx1, __shfl_xor_sync(0xffffffffu, mx1, 1));
            mx1 = fmaxf(mx1, __shfl_xor_sync(0xffffffffu, mx1, 2));

            const float mn0 = fmaxf(m0, mx0), mn1 = fmaxf(m1, mx1);
            const float a0 = __expf(m0 - mn0), a1 = __expf(m1 - mn1);
            m0 = mn0; m1 = mn1;

            float rs0 = 0.0f, rs1 = 0.0f;
#pragma unroll
            for (int j = 0; j < 8; j++) {
                s[j][0] = __expf(s[j][0] - mn0); rs0 += s[j][0];
                s[j][1] = __expf(s[j][1] - mn0); rs0 += s[j][1];
                s[j][2] = __expf(s[j][2] - mn1); rs1 += s[j][2];
                s[j][3] = __expf(s[j][3] - mn1); rs1 += s[j][3];
            }
            rs0 += __shfl_xor_sync(0xffffffffu, rs0, 1);
            rs0 += __shfl_xor_sync(0xffffffffu, rs0, 2);
            rs1 += __shfl_xor_sync(0xffffffffu, rs1, 1);
            rs1 += __shfl_xor_sync(0xffffffffu, rs1, 2);
            l0 = l0 * a0 + rs0;
            l1 = l1 * a1 + rs1;

#pragma unroll
            for (int j = 0; j < 16; j++) {
                o[j][0] *= a0; o[j][1] *= a0;
                o[j][2] *= a1; o[j][3] *= a1;
            }

            // ---- O += P V (fp16x2: P split, single vh) ----
#pragma unroll
            for (int kk = 0; kk < 4; kk++) {
                const float* sA = s[2 * kk];
                const float* sB = s[2 * kk + 1];
                uint32_t pa_h[4], pa_l[4];
                {
                    __half2 h;
                    h = __floats2half2_rn(sA[0], sA[1]);
                    pa_h[0] = *reinterpret_cast<uint32_t*>(&h);
                    pa_l[0] = pack_h2(sA[0] - __half2float(h.x), sA[1] - __half2float(h.y));
                    h = __floats2half2_rn(sA[2], sA[3]);
                    pa_h[1] = *reinterpret_cast<uint32_t*>(&h);
                    pa_l[1] = pack_h2(sA[2] - __half2float(h.x), sA[3] - __half2float(h.y));
                    h = __floats2half2_rn(sB[0], sB[1]);
                    pa_h[2] = *reinterpret_cast<uint32_t*>(&h);
                    pa_l[2] = pack_h2(sB[0] - __half2float(h.x), sB[1] - __half2float(h.y));
                    h = __floats2half2_rn(sB[2], sB[3]);
                    pa_h[3] = *reinterpret_cast<uint32_t*>(&h);
                    pa_l[3] = pack_h2(sB[2] - __half2float(h.x), sB[3] - __half2float(h.y));
                }
                const int vkrow = kk * 16 + tkrow;
#pragma unroll
                for (int gn = 0; gn < 8; gn++) {
                    const int dcol = gn * 16 + tdh;
                    const uint32_t voff = (uint32_t)(dcol >> 5) * 4096 +
                                          sw_off(vkrow, (dcol >> 3) & 3);
                    uint32_t vbh[4];
                    LDSM4T(vbh, buf + 16384 + voff);
#pragma unroll
                    for (int h = 0; h < 2; h++) {
                        float* d = o[gn * 2 + h];
                        MMA16816(d, pa_h, vbh[h], vbh[2 + h]);
                        MMA16816(d, pa_l, vbh[h], vbh[2 + h]);
                    }
                }
            }
        }
        __syncthreads();
    }

    // Epilogue: ctx = O / l, split fp16 hi/lo, [B,S,E] row-major
    const float inv0 = 1.0f / l0, inv1 = 1.0f / l1;
    const int row0 = q0 + wm16 + gr;
    const size_t base0 = (size_t)(bb * SEQ + row0) * EMB + hcol;
    const size_t base1 = base0 + (size_t)8 * EMB;
#pragma unroll
    for (int j = 0; j < 16; j++) {
        const int d0 = j * 8 + 2 * t4;
        float v0 = o[j][0] * inv0, v1 = o[j][1] * inv0;
        __half2 h2 = __floats2half2_rn(v0, v1);
        *(__half2*)(cth + base0 + d0) = h2;
        *(__half2*)(ctl + base0 + d0) =
            __floats2half2_rn(v0 - __half2float(h2.x), v1 - __half2float(h2.y));
        float v2 = o[j][2] * inv1, v3 = o[j][3] * inv1;
        h2 = __floats2half2_rn(v2, v3);
        *(__half2*)(cth + base1 + d0) = h2;
        *(__half2*)(ctl + base1 + d0) =
            __floats2half2_rn(v2 - __half2float(h2.x), v3 - __half2float(h2.y));
    }
}

// ---------------------------------------------------------------------------
extern "C" void kernel_launch(void* const* d_in, const int* in_sizes, int n_in,
                              void* d_out, int out_size)
{
    const float* x  = (const float*)d_in[0];
    const float* Wq = (const float*)d_in[2];
    const float* bq = (const float*)d_in[3];
    const float* Wk = (const float*)d_in[4];
    const float* bk = (const float*)d_in[5];
    const float* Wv = (const float*)d_in[6];
    const float* bv = (const float*)d_in[7];
    const float* Wo = (const float*)d_in[8];
    const float* bo = (const float*)d_in[9];
    float* out = (float*)d_out;

    __half *xh, *xl, *wp, *qh, *ql, *kh, *vh;
    cudaGetSymbolAddress((void**)&xh, g_xh);
    cudaGetSymbolAddress((void**)&xl, g_xl);
    cudaGetSymbolAddress((void**)&wp, g_w);
    cudaGetSymbolAddress((void**)&qh, g_qh);
    cudaGetSymbolAddress((void**)&ql, g_ql);
    cudaGetSymbolAddress((void**)&kh, g_kh);
    cudaGetSymbolAddress((void**)&vh, g_vh);

    const float* Ws[4] = {Wq, Wk, Wv, Wo};
    const int nX4 = MROWS * EMB / 4;
    const int nW4 = EMB * EMB / 4;

    split_f16<<<(nX4 + 255) / 256, 256>>>(x, xh, xl, nX4);
    for (int i = 0; i < 4; i++)
        conv_f16<<<(nW4 + 255) / 256, 256>>>(Ws[i], wp + (size_t)i * EMB * EMB, nW4);

    cudaFuncSetAttribute(gemm_f16x2, cudaFuncAttributeMaxDynamicSharedMemorySize,
                         GEMM_DSMEM);
    dim3 gg(EMB / 128, MROWS / 128);  // (16, 64)

    const float qscale = 0.08838834764831845f;  // 1/sqrt(128), folded into Q
    gemm_f16x2<<<gg, 256, GEMM_DSMEM>>>(xh, xl, wp + 0 * (size_t)EMB * EMB, bq,
                                        nullptr, qh, ql, 1, qscale);
    gemm_f16x2<<<gg, 256, GEMM_DSMEM>>>(xh, xl, wp + 1 * (size_t)EMB * EMB, bk,
                                        nullptr, kh, nullptr, 2, 1.0f);
    gemm_f16x2<<<gg, 256, GEMM_DSMEM>>>(xh, xl, wp + 2 * (size_t)EMB * EMB, bv,
                                        nullptr, vh, nullptr, 2, 1.0f);

    cudaFuncSetAttribute(flash_f16, cudaFuncAttributeMaxDynamicSharedMemorySize,
                         FL_SMEM);
    // flash writes ctx into xh/xl (X dead after QKV GEMMs)
    flash_f16<<<dim3(SEQ / 128, BATCH * HEADS), 256, FL_SMEM>>>(qh, ql, kh, vh, xh, xl);

    gemm_f16x2<<<gg, 256, GEMM_DSMEM>>>(xh, xl, wp + 3 * (size_t)EMB * EMB, bo,
                                        out, nullptr, nullptr, 0, 1.0f);
}

// round 6
// speedup vs baseline: 4.3706x; 1.0177x over previous
#include <cuda_runtime.h>
#include <cuda_fp16.h>
#include <math.h>
#include <cstdint>

// Problem constants
#define EMB    2048
#define HEADS  16
#define HEADD  128
#define BATCH  4
#define SEQ    2048
#define MROWS  (BATCH * SEQ)        // 8192
#define KDIM   EMB

// ---------------------------------------------------------------------------
// Scratch (device globals: allocation-free)
// ---------------------------------------------------------------------------
__device__ __half g_xh[(size_t)MROWS * EMB];   // X hi (reused as ctx hi)
__device__ __half g_xl[(size_t)MROWS * EMB];   // X lo (reused as ctx lo)
__device__ __half g_w[4][(size_t)EMB * EMB];   // Wq,Wk,Wv,Wo (fp16)
__device__ __half g_qh[(size_t)MROWS * EMB];   // [B,S,H,D] row-major
__device__ __half g_ql[(size_t)MROWS * EMB];
__device__ __half g_kh[(size_t)MROWS * EMB];
__device__ __half g_vh[(size_t)MROWS * EMB];

// ---------------------------------------------------------------------------
// PTX helpers (compute_103-safe: no 'a' features)
// ---------------------------------------------------------------------------
__device__ __forceinline__ uint32_t smem_u32(const void* p) {
    uint32_t a;
    asm("{ .reg .u64 t; cvta.to.shared.u64 t, %1; cvt.u32.u64 %0, t; }" : "=r"(a) : "l"(p));
    return a;
}

#define CP_ASYNC16(dst, src) \
    asm volatile("cp.async.cg.shared.global [%0], [%1], 16;" :: "r"(dst), "l"(src) : "memory")
#define CP_COMMIT() asm volatile("cp.async.commit_group;" ::: "memory")
#define CP_WAIT1()  asm volatile("cp.async.wait_group 1;" ::: "memory")
#define CP_WAIT2()  asm volatile("cp.async.wait_group 2;" ::: "memory")

#define LDSM4(r, a)                                                              \
    asm volatile("ldmatrix.sync.aligned.m8n8.x4.shared.b16 {%0,%1,%2,%3}, [%4];" \
        : "=r"((r)[0]), "=r"((r)[1]), "=r"((r)[2]), "=r"((r)[3]) : "r"(a))

#define LDSM4T(r, a)                                                                   \
    asm volatile("ldmatrix.sync.aligned.m8n8.x4.trans.shared.b16 {%0,%1,%2,%3}, [%4];" \
        : "=r"((r)[0]), "=r"((r)[1]), "=r"((r)[2]), "=r"((r)[3]) : "r"(a))

#define MMA16816(d, a, b0, b1)                                                   \
    asm volatile("mma.sync.aligned.m16n8k16.row.col.f32.f16.f16.f32 "            \
        "{%0,%1,%2,%3}, {%4,%5,%6,%7}, {%8,%9}, {%0,%1,%2,%3};"                  \
        : "+f"((d)[0]), "+f"((d)[1]), "+f"((d)[2]), "+f"((d)[3])                  \
        : "r"((a)[0]), "r"((a)[1]), "r"((a)[2]), "r"((a)[3]), "r"(b0), "r"(b1))

// Swizzled byte offset within a [rows][32] fp16 tile (64B rows, 4 x 16B units)
__device__ __forceinline__ uint32_t sw_off(int row, int unit) {
    return (uint32_t)(row * 64) + ((uint32_t)(unit ^ ((row >> 1) & 3)) << 4);
}

__device__ __forceinline__ uint32_t pack_h2(float a, float b) {
    __half2 t = __floats2half2_rn(a, b);
    return *reinterpret_cast<uint32_t*>(&t);
}

// ---------------------------------------------------------------------------
// Split fp32 -> fp16 hi + fp16 lo  (vectorized x4)
// ---------------------------------------------------------------------------
__global__ void split_f16(const float* __restrict__ in,
                          __half* __restrict__ hi,
                          __half* __restrict__ lo, int n4)
{
    int i = blockIdx.x * blockDim.x + threadIdx.x;
    if (i >= n4) return;
    float4 v = ((const float4*)in)[i];
    __half h0 = __float2half_rn(v.x);
    __half h1 = __float2half_rn(v.y);
    __half h2 = __float2half_rn(v.z);
    __half h3 = __float2half_rn(v.w);
    __half2* hp = (__half2*)hi;
    __half2* lp = (__half2*)lo;
    hp[2 * i]     = __half2(h0, h1);
    hp[2 * i + 1] = __half2(h2, h3);
    lp[2 * i]     = __floats2half2_rn(v.x - __half2float(h0), v.y - __half2float(h1));
    lp[2 * i + 1] = __floats2half2_rn(v.z - __half2float(h2), v.w - __half2float(h3));
}

// fp32 -> fp16 (hi only), for weights
__global__ void conv_f16(const float* __restrict__ in, __half* __restrict__ hi, int n4)
{
    int i = blockIdx.x * blockDim.x + threadIdx.x;
    if (i >= n4) return;
    float4 v = ((const float4*)in)[i];
    __half2* hp = (__half2*)hi;
    hp[2 * i]     = __floats2half2_rn(v.x, v.y);
    hp[2 * i + 1] = __floats2half2_rn(v.z, v.w);
}

// ---------------------------------------------------------------------------
// fp16x2 mma.sync GEMM: C[m,n] = (sum_k (Ah+Al)[m,k]*B[n,k] + bias[n]) * scale
// mode 0: -> fp32 Cf.   mode 1: -> fp16 hi/lo (Ch, Cl).   mode 2: -> fp16 Ch.
// CTA 128x128, K-chunk 32, 8 warps (warp tile 32x64), 4-stage cp.async,
// 2 CTAs/SM (reg-capped) so cross-CTA MMA issue hides syncs/LDSM/epilogue.
// ---------------------------------------------------------------------------
#define TILE_B2   8192                  // one 128x32 fp16 tile
#define STAGE_B2  (3 * TILE_B2)         // Ah, Al, Bh = 24 KB
#define NSTAGE    4
#define GEMM_DSMEM (NSTAGE * STAGE_B2 + 1024)
#define NCHUNK    (KDIM / 32)           // 64

__device__ __forceinline__ void load_stage(
    const __half* __restrict__ Ah, const __half* __restrict__ Al,
    const __half* __restrict__ Bh,
    int m0, int n0, int kc, uint32_t sbase, int tid)
{
    const int unit  = tid & 3;
    const int rbase = tid >> 2;          // 0..63
#pragma unroll
    for (int p = 0; p < 2; p++) {
        const int row = rbase + p * 64;
        const uint32_t so = sw_off(row, unit);
        const size_t ga = (size_t)(m0 + row) * KDIM + kc + unit * 8;
        const size_t gb = (size_t)(n0 + row) * KDIM + kc + unit * 8;
        CP_ASYNC16(sbase + so,               Ah + ga);
        CP_ASYNC16(sbase + TILE_B2 + so,     Al + ga);
        CP_ASYNC16(sbase + 2 * TILE_B2 + so, Bh + gb);
    }
}

__global__ __launch_bounds__(256, 2)
void gemm_f16x2(const __half* __restrict__ Ah, const __half* __restrict__ Al,
                const __half* __restrict__ Bh,
                const float* __restrict__ bias, float* __restrict__ Cf,
                __half* __restrict__ Ch, __half* __restrict__ Cl,
                int mode, float scale)
{
    extern __shared__ char dyn[];
    const int tid  = threadIdx.x;
    const int lane = tid & 31;
    const int w    = tid >> 5;
    const int m0   = blockIdx.y * 128;
    const int n0   = blockIdx.x * 128;
    const int wm   = (w & 3) * 32;
    const int wn   = (w >> 2) * 64;

    uint32_t base = (smem_u32(dyn) + 1023u) & ~1023u;

    const int r8   = lane & 7;
    const int mat  = lane >> 3;
    const int lrow = ((mat & 1) << 3) + r8;
    const int lch  = mat >> 1;

    float acc[2][8][4];
#pragma unroll
    for (int i = 0; i < 2; i++)
#pragma unroll
        for (int j = 0; j < 8; j++)
#pragma unroll
            for (int c = 0; c < 4; c++) acc[i][j][c] = 0.0f;

    load_stage(Ah, Al, Bh, m0, n0, 0,  base,                tid); CP_COMMIT();
    load_stage(Ah, Al, Bh, m0, n0, 32, base + STAGE_B2,     tid); CP_COMMIT();
    load_stage(Ah, Al, Bh, m0, n0, 64, base + 2 * STAGE_B2, tid); CP_COMMIT();

    for (int i = 0; i < NCHUNK; i++) {
        const uint32_t sb = base + (uint32_t)(i % NSTAGE) * STAGE_B2;
        CP_WAIT2();
        __syncthreads();
        if (i + 3 < NCHUNK)
            load_stage(Ah, Al, Bh, m0, n0, (i + 3) * 32,
                       base + (uint32_t)((i + 3) % NSTAGE) * STAGE_B2, tid);
        CP_COMMIT();

        const uint32_t sAh = sb, sAl = sb + TILE_B2, sBh = sb + 2 * TILE_B2;

#pragma unroll
        for (int ks = 0; ks < 2; ks++) {
            uint32_t ah[2][4], al[2][4], bh[4][4];
#pragma unroll
            for (int mi = 0; mi < 2; mi++) {
                const uint32_t off = sw_off(wm + mi * 16 + lrow, ks * 2 + lch);
                LDSM4(ah[mi], sAh + off);
                LDSM4(al[mi], sAl + off);
            }
#pragma unroll
            for (int g = 0; g < 4; g++) {
                const uint32_t off = sw_off(wn + g * 16 + lrow, ks * 2 + lch);
                LDSM4(bh[g], sBh + off);
            }
#pragma unroll
            for (int mi = 0; mi < 2; mi++)
#pragma unroll
                for (int g = 0; g < 4; g++)
#pragma unroll
                    for (int h = 0; h < 2; h++) {
                        float* d = acc[mi][g * 2 + h];
                        MMA16816(d, ah[mi], bh[g][h], bh[g][2 + h]);
                        MMA16816(d, al[mi], bh[g][h], bh[g][2 + h]);
                    }
        }
    }

    // Epilogue
    const int qr = lane >> 2;
    const int qc = (lane & 3) * 2;
#pragma unroll
    for (int mi = 0; mi < 2; mi++) {
#pragma unroll
        for (int nj = 0; nj < 8; nj++) {
            const int col = n0 + wn + nj * 8 + qc;
            const float2 bb = *(const float2*)&bias[col];
            const int row0 = m0 + wm + mi * 16 + qr;
            float v00 = (acc[mi][nj][0] + bb.x) * scale;
            float v01 = (acc[mi][nj][1] + bb.y) * scale;
            float v10 = (acc[mi][nj][2] + bb.x) * scale;
            float v11 = (acc[mi][nj][3] + bb.y) * scale;
            if (mode == 0) {
                *(float2*)&Cf[(size_t)row0 * EMB + col]       = make_float2(v00, v01);
                *(float2*)&Cf[(size_t)(row0 + 8) * EMB + col] = make_float2(v10, v11);
            } else if (mode == 1) {
                __half2 h2 = __floats2half2_rn(v00, v01);
                *(__half2*)(Ch + (size_t)row0 * EMB + col) = h2;
                *(__half2*)(Cl + (size_t)row0 * EMB + col) =
                    __floats2half2_rn(v00 - __half2float(h2.x), v01 - __half2float(h2.y));
                h2 = __floats2half2_rn(v10, v11);
                *(__half2*)(Ch + (size_t)(row0 + 8) * EMB + col) = h2;
                *(__half2*)(Cl + (size_t)(row0 + 8) * EMB + col) =
                    __floats2half2_rn(v10 - __half2float(h2.x), v11 - __half2float(h2.y));
            } else {
                *(__half2*)(Ch + (size_t)row0 * EMB + col)       = __floats2half2_rn(v00, v01);
                *(__half2*)(Ch + (size_t)(row0 + 8) * EMB + col) = __floats2half2_rn(v10, v11);
            }
        }
    }
}

// ---------------------------------------------------------------------------
// Tensor-core flash attention, fp16x2, causal. 1/sqrt(d) pre-folded into Q.
// Q-tile 128, KV-tile 64, 8 warps each owning a 16x64 score stripe.
// 3-buffer KV ring -> single __syncthreads per KV block.
// ---------------------------------------------------------------------------
#define FL_SMEM (65536 + 3 * 32768)     // Q (hi+lo 64KB) + 3 KV buffers (32KB each)

__global__ __launch_bounds__(256, 1)
void flash_f16(const __half* __restrict__ qh, const __half* __restrict__ ql,
               const __half* __restrict__ kh, const __half* __restrict__ vh,
               __half* __restrict__ cth, __half* __restrict__ ctl)
{
    extern __shared__ char smf[];
    const int tid  = threadIdx.x;
    const int lane = tid & 31;
    const int w    = tid >> 5;
    const int wm16 = w * 16;

    const int bx  = gridDim.x - 1 - blockIdx.x;   // heavy blocks first
    const int q0  = bx * 128;
    const int bh_ = blockIdx.y;
    const int bb  = bh_ >> 4;
    const int hh  = bh_ & 15;
    const int hcol = hh * 128;
    const int nkb = 2 * bx + 2;

    const uint32_t sQh = smem_u32(smf);
    const uint32_t sQl = sQh + 32768;
    const uint32_t sKV = sQh + 65536;     // ring buf b at sKV + b*32768: Kh, Vh

    const int r8   = lane & 7;
    const int mat  = lane >> 3;
    const int lrow = ((mat & 1) << 3) + r8;
    const int lch  = mat >> 1;
    const int tkrow = (lane & 7) + ((lane >> 4) << 3);
    const int tdh   = ((lane >> 3) & 1) << 3;
    const int t4 = lane & 3;
    const int gr = lane >> 2;

    // Prologue: Q (hi+lo) + KV block 0 -> ring slot 0
    {
        const int unit = tid & 3;
        const int rr   = tid >> 2;       // 0..63
#pragma unroll
        for (int p = 0; p < 2; p++) {
            const int row = rr + p * 64;
            const size_t grow = (size_t)(bb * SEQ + q0 + row) * EMB + hcol + unit * 8;
#pragma unroll
            for (int c4 = 0; c4 < 4; c4++) {
                const uint32_t so = (uint32_t)c4 * 8192 + sw_off(row, unit);
                CP_ASYNC16(sQh + so, qh + grow + c4 * 32);
                CP_ASYNC16(sQl + so, ql + grow + c4 * 32);
            }
        }
        const size_t g0 = (size_t)(bb * SEQ + rr) * EMB + hcol + unit * 8;
#pragma unroll
        for (int c4 = 0; c4 < 4; c4++) {
            const uint32_t so = (uint32_t)c4 * 4096 + sw_off(rr, unit);
            CP_ASYNC16(sKV + so,         kh + g0 + c4 * 32);
            CP_ASYNC16(sKV + 16384 + so, vh + g0 + c4 * 32);
        }
        CP_COMMIT();
    }

    float o[16][4];
#pragma unroll
    for (int j = 0; j < 16; j++)
#pragma unroll
        for (int c = 0; c < 4; c++) o[j][c] = 0.0f;
    float m0 = -1e30f, m1 = -1e30f, l0 = 0.0f, l1 = 0.0f;

    int rb = 0, rbn = 1;                 // ring slot of kb, kb+1
    for (int kb = 0; kb < nkb; kb++) {
        const uint32_t buf = sKV + (uint32_t)rb * 32768;

        // Prefetch kb+1 into ring slot rbn (read last at iter kb-2; the
        // __syncthreads at iters kb-1 and kb guarantee all warps are done).
        if (kb + 1 < nkb) {
            const uint32_t nbuf = sKV + (uint32_t)rbn * 32768;
            const int unit = tid & 3;
            const int rr   = tid >> 2;
            const size_t grow = (size_t)(bb * SEQ + (kb + 1) * 64 + rr) * EMB + hcol + unit * 8;
#pragma unroll
            for (int c4 = 0; c4 < 4; c4++) {
                const uint32_t so = (uint32_t)c4 * 4096 + sw_off(rr, unit);
                CP_ASYNC16(nbuf + so,         kh + grow + c4 * 32);
                CP_ASYNC16(nbuf + 16384 + so, vh + grow + c4 * 32);
            }
        }
        CP_COMMIT();
        CP_WAIT1();
        __syncthreads();

        if (kb * 64 <= q0 + wm16 + 15) {
            float s[8][4];
#pragma unroll
            for (int j = 0; j < 8; j++)
#pragma unroll
                for (int c = 0; c < 4; c++) s[j][c] = 0.0f;

            // ---- S = Q K^T (fp16x2: qh + ql, single kh) ----
#pragma unroll
            for (int ks = 0; ks < 8; ks++) {
                const uint32_t qoff = (uint32_t)(ks >> 1) * 8192 +
                                      sw_off(wm16 + lrow, (ks & 1) * 2 + lch);
                uint32_t qa_h[4], qa_l[4];
                LDSM4(qa_h, sQh + qoff);
                LDSM4(qa_l, sQl + qoff);
#pragma unroll
                for (int g = 0; g < 4; g++) {
                    const uint32_t koff = (uint32_t)(ks >> 1) * 4096 +
                                          sw_off(g * 16 + lrow, (ks & 1) * 2 + lch);
                    uint32_t kbh[4];
                    LDSM4(kbh, buf + koff);
#pragma unroll
                    for (int h = 0; h < 2; h++) {
                        float* d = s[g * 2 + h];
                        MMA16816(d, qa_h, kbh[h], kbh[2 + h]);
                        MMA16816(d, qa_l, kbh[h], kbh[2 + h]);
                    }
                }
            }

            // causal mask (scale already folded into Q)
            if (kb * 64 + 63 > q0 + wm16) {
                const int row0 = q0 + wm16 + gr;
#pragma unroll
                for (int j = 0; j < 8; j++) {
                    const int col = kb * 64 + (j >> 1) * 16 + (j & 1) * 8 + 2 * t4;
                    if (col > row0)         s[j][0] = -1e30f;
                    if (col + 1 > row0)     s[j][1] = -1e30f;
                    if (col > row0 + 8)     s[j][2] = -1e30f;
                    if (col + 1 > row0 + 8) s[j][3] = -1e30f;
                }
            }

            // ---- online softmax ----
            float mx0 = -1e30f, mx1 = -1e30f;
#pragma unroll
            for (int j = 0; j < 8; j++) {
                mx0 = fmaxf(mx0, fmaxf(s[j][0], s[j][1]));
                mx1 = fmaxf(mx1, fmaxf(s[j][2], s[j][3]));
            }
            mx0 = fmaxf(mx0, __shfl_xor_sync(0xffffffffu, mx0, 1));
            mx0 = fmaxf(mx0, __shfl_xor_sync(0xffffffffu, mx0, 2));
            mx1 = fmaxf(mx1, __shfl_xor_sync(0xffffffffu, mx1, 1));
            mx1 = fmaxf(mx1, __shfl_xor_sync(0xffffffffu, mx1, 2));

            const float mn0 = fmaxf(m0, mx0), mn1 = fmaxf(m1, mx1);
            const float a0 = __expf(m0 - mn0), a1 = __expf(m1 - mn1);
            m0 = mn0; m1 = mn1;

            float rs0 = 0.0f, rs1 = 0.0f;
#pragma unroll
            for (int j = 0; j < 8; j++) {
                s[j][0] = __expf(s[j][0] - mn0); rs0 += s[j][0];
                s[j][1] = __expf(s[j][1] - mn0); rs0 += s[j][1];
                s[j][2] = __expf(s[j][2] - mn1); rs1 += s[j][2];
                s[j][3] = __expf(s[j][3] - mn1); rs1 += s[j][3];
            }
            rs0 += __shfl_xor_sync(0xffffffffu, rs0, 1);
            rs0 += __shfl_xor_sync(0xffffffffu, rs0, 2);
            rs1 += __shfl_xor_sync(0xffffffffu, rs1, 1);
            rs1 += __shfl_xor_sync(0xffffffffu, rs1, 2);
            l0 = l0 * a0 + rs0;
            l1 = l1 * a1 + rs1;

#pragma unroll
            for (int j = 0; j < 16; j++) {
                o[j][0] *= a0; o[j][1] *= a0;
                o[j][2] *= a1; o[j][3] *= a1;
            }

            // ---- O += P V (fp16x2: P split, single vh) ----
#pragma unroll
            for (int kk = 0; kk < 4; kk++) {
                const float* sA = s[2 * kk];
                const float* sB = s[2 * kk + 1];
                uint32_t pa_h[4], pa_l[4];
                {
                    __half2 h;
                    h = __floats2half2_rn(sA[0], sA[1]);
                    pa_h[0] = *reinterpret_cast<uint32_t*>(&h);
                    pa_l[0] = pack_h2(sA[0] - __half2float(h.x), sA[1] - __half2float(h.y));
                    h = __floats2half2_rn(sA[2], sA[3]);
                    pa_h[1] = *reinterpret_cast<uint32_t*>(&h);
                    pa_l[1] = pack_h2(sA[2] - __half2float(h.x), sA[3] - __half2float(h.y));
                    h = __floats2half2_rn(sB[0], sB[1]);
                    pa_h[2] = *reinterpret_cast<uint32_t*>(&h);
                    pa_l[2] = pack_h2(sB[0] - __half2float(h.x), sB[1] - __half2float(h.y));
                    h = __floats2half2_rn(sB[2], sB[3]);
                    pa_h[3] = *reinterpret_cast<uint32_t*>(&h);
                    pa_l[3] = pack_h2(sB[2] - __half2float(h.x), sB[3] - __half2float(h.y));
                }
                const int vkrow = kk * 16 + tkrow;
#pragma unroll
                for (int gn = 0; gn < 8; gn++) {
                    const int dcol = gn * 16 + tdh;
                    const uint32_t voff = (uint32_t)(dcol >> 5) * 4096 +
                                          sw_off(vkrow, (dcol >> 3) & 3);
                    uint32_t vbh[4];
                    LDSM4T(vbh, buf + 16384 + voff);
#pragma unroll
                    for (int h = 0; h < 2; h++) {
                        float* d = o[gn * 2 + h];
                        MMA16816(d, pa_h, vbh[h], vbh[2 + h]);
                        MMA16816(d, pa_l, vbh[h], vbh[2 + h]);
                    }
                }
            }
        }
        rb = rbn;
        rbn = (rbn == 2) ? 0 : rbn + 1;
    }

    // Epilogue: ctx = O / l, split fp16 hi/lo, [B,S,E] row-major
    const float inv0 = 1.0f / l0, inv1 = 1.0f / l1;
    const int row0 = q0 + wm16 + gr;
    const size_t base0 = (size_t)(bb * SEQ + row0) * EMB + hcol;
    const size_t base1 = base0 + (size_t)8 * EMB;
#pragma unroll
    for (int j = 0; j < 16; j++) {
        const int d0 = j * 8 + 2 * t4;
        float v0 = o[j][0] * inv0, v1 = o[j][1] * inv0;
        __half2 h2 = __floats2half2_rn(v0, v1);
        *(__half2*)(cth + base0 + d0) = h2;
        *(__half2*)(ctl + base0 + d0) =
            __floats2half2_rn(v0 - __half2float(h2.x), v1 - __half2float(h2.y));
        float v2 = o[j][2] * inv1, v3 = o[j][3] * inv1;
        h2 = __floats2half2_rn(v2, v3);
        *(__half2*)(cth + base1 + d0) = h2;
        *(__half2*)(ctl + base1 + d0) =
            __floats2half2_rn(v2 - __half2float(h2.x), v3 - __half2float(h2.y));
    }
}

// ---------------------------------------------------------------------------
extern "C" void kernel_launch(void* const* d_in, const int* in_sizes, int n_in,
                              void* d_out, int out_size)
{
    const float* x  = (const float*)d_in[0];
    const float* Wq = (const float*)d_in[2];
    const float* bq = (const float*)d_in[3];
    const float* Wk = (const float*)d_in[4];
    const float* bk = (const float*)d_in[5];
    const float* Wv = (const float*)d_in[6];
    const float* bv = (const float*)d_in[7];
    const float* Wo = (const float*)d_in[8];
    const float* bo = (const float*)d_in[9];
    float* out = (float*)d_out;

    __half *xh, *xl, *wp, *qh, *ql, *kh, *vh;
    cudaGetSymbolAddress((void**)&xh, g_xh);
    cudaGetSymbolAddress((void**)&xl, g_xl);
    cudaGetSymbolAddress((void**)&wp, g_w);
    cudaGetSymbolAddress((void**)&qh, g_qh);
    cudaGetSymbolAddress((void**)&ql, g_ql);
    cudaGetSymbolAddress((void**)&kh, g_kh);
    cudaGetSymbolAddress((void**)&vh, g_vh);

    const float* Ws[4] = {Wq, Wk, Wv, Wo};
    const int nX4 = MROWS * EMB / 4;
    const int nW4 = EMB * EMB / 4;

    split_f16<<<(nX4 + 255) / 256, 256>>>(x, xh, xl, nX4);
    for (int i = 0; i < 4; i++)
        conv_f16<<<(nW4 + 255) / 256, 256>>>(Ws[i], wp + (size_t)i * EMB * EMB, nW4);

    cudaFuncSetAttribute(gemm_f16x2, cudaFuncAttributeMaxDynamicSharedMemorySize,
                         GEMM_DSMEM);
    dim3 gg(EMB / 128, MROWS / 128);  // (16, 64)

    const float qscale = 0.08838834764831845f;  // 1/sqrt(128), folded into Q
    gemm_f16x2<<<gg, 256, GEMM_DSMEM>>>(xh, xl, wp + 0 * (size_t)EMB * EMB, bq,
                                        nullptr, qh, ql, 1, qscale);
    gemm_f16x2<<<gg, 256, GEMM_DSMEM>>>(xh, xl, wp + 1 * (size_t)EMB * EMB, bk,
                                        nullptr, kh, nullptr, 2, 1.0f);
    gemm_f16x2<<<gg, 256, GEMM_DSMEM>>>(xh, xl, wp + 2 * (size_t)EMB * EMB, bv,
                                        nullptr, vh, nullptr, 2, 1.0f);

    cudaFuncSetAttribute(flash_f16, cudaFuncAttributeMaxDynamicSharedMemorySize,
                         FL_SMEM);
    // flash writes ctx into xh/xl (X dead after QKV GEMMs)
    flash_f16<<<dim3(SEQ / 128, BATCH * HEADS), 256, FL_SMEM>>>(qh, ql, kh, vh, xh, xl);

    gemm_f16x2<<<gg, 256, GEMM_DSMEM>>>(xh, xl, wp + 3 * (size_t)EMB * EMB, bo,
                                        out, nullptr, nullptr, 0, 1.0f);
}